// round 1
// baseline (speedup 1.0000x reference)
#include <cuda_runtime.h>
#include <cuda_bf16.h>
#include <math.h>
#include <float.h>

#define NN 100000
#define IN_DIM 256
#define L1_OUT 64      // HEADS*HID
#define HEADS 8
#define HID 8
#define OUT_DIM 40
#define EMAX 1700000   // 1.6M edges + 100k self loops
#define NEG_SLOPE 0.2f

// ---------------- scratch (static __device__, no allocs allowed) ----------------
__device__ float    g_xl1[NN * L1_OUT];
__device__ float    g_xr1[NN * L1_OUT];
__device__ float    g_out1[NN * L1_OUT];
__device__ float    g_logit1[EMAX * HEADS];
__device__ unsigned g_max1[NN * HEADS];
__device__ float    g_sum1[NN * HEADS];

__device__ float    g_hl2[NN * OUT_DIM];
__device__ float    g_hr2[NN * OUT_DIM];
__device__ float    g_logit2[EMAX];
__device__ unsigned g_max2[NN];
__device__ float    g_sum2[NN];
__device__ float    g_out2[NN * OUT_DIM];

// ---------------- order-preserving float<->uint encoding for atomicMax ----------
__device__ __forceinline__ unsigned fenc(float f) {
    unsigned u = __float_as_uint(f);
    return (u & 0x80000000u) ? ~u : (u | 0x80000000u);
}
__device__ __forceinline__ float fdec(unsigned u) {
    u = (u & 0x80000000u) ? (u & 0x7fffffffu) : ~u;
    return __uint_as_float(u);
}

// ---------------- init: zero accumulators; 0u is below every encoded float ------
__global__ void init_kernel() {
    int i = blockIdx.x * blockDim.x + threadIdx.x;
    if (i < NN * L1_OUT) g_out1[i] = 0.f;
    if (i < NN * OUT_DIM) g_out2[i] = 0.f;
    if (i < NN * HEADS) { g_sum1[i] = 0.f; g_max1[i] = 0u; }
    if (i < NN)         { g_sum2[i] = 0.f; g_max2[i] = 0u; }
}

// ---------------- GEMM1: [N,256] @ [256,64|64] -> g_xl1, g_xr1 -------------------
// BM=64, BN=128 (xl cols 0..63, xr cols 64..127), BK=16, 256 threads, 8x4 reg tile
__global__ void gemm1_kernel(const float* __restrict__ x,
                             const float* __restrict__ Wl, const float* __restrict__ bl,
                             const float* __restrict__ Wr, const float* __restrict__ br) {
    __shared__ float As[16][64];
    __shared__ float Bs[16][128];
    const int tid = threadIdx.x;
    const int block_row = blockIdx.x * 64;
    const int tx = tid & 31;   // col group: cols tx*4 .. tx*4+3
    const int ty = tid >> 5;   // row group: rows ty*8 .. ty*8+7

    float acc[8][4];
#pragma unroll
    for (int i = 0; i < 8; i++)
#pragma unroll
        for (int j = 0; j < 4; j++) acc[i][j] = 0.f;

    const int ar = tid >> 2;           // 0..63
    const int ak = (tid & 3) * 4;      // 0,4,8,12
    const int kr = tid >> 4;           // 0..15
    const int bc = (tid & 15) * 8;     // 0..120

    for (int k0 = 0; k0 < IN_DIM; k0 += 16) {
        int gr = block_row + ar;
        float4 av = make_float4(0.f, 0.f, 0.f, 0.f);
        if (gr < NN) av = *(const float4*)(x + (long)gr * IN_DIM + k0 + ak);
        As[ak + 0][ar] = av.x; As[ak + 1][ar] = av.y;
        As[ak + 2][ar] = av.z; As[ak + 3][ar] = av.w;

        const float* Bsrc = (bc < 64) ? (Wl + (k0 + kr) * 64 + bc)
                                      : (Wr + (k0 + kr) * 64 + bc - 64);
        float4 b0 = *(const float4*)(Bsrc);
        float4 b1 = *(const float4*)(Bsrc + 4);
        *(float4*)&Bs[kr][bc] = b0;
        *(float4*)&Bs[kr][bc + 4] = b1;
        __syncthreads();

#pragma unroll
        for (int kk = 0; kk < 16; kk++) {
            float4 a0 = *(float4*)&As[kk][ty * 8];
            float4 a1 = *(float4*)&As[kk][ty * 8 + 4];
            float4 b  = *(float4*)&Bs[kk][tx * 4];
            float ra[8] = {a0.x, a0.y, a0.z, a0.w, a1.x, a1.y, a1.z, a1.w};
            float rb[4] = {b.x, b.y, b.z, b.w};
#pragma unroll
            for (int i = 0; i < 8; i++)
#pragma unroll
                for (int j = 0; j < 4; j++) acc[i][j] += ra[i] * rb[j];
        }
        __syncthreads();
    }

#pragma unroll
    for (int i = 0; i < 8; i++) {
        int r = block_row + ty * 8 + i;
        if (r >= NN) continue;
#pragma unroll
        for (int j = 0; j < 4; j++) {
            int c = tx * 4 + j;
            float v = acc[i][j];
            if (c < 64) g_xl1[r * 64 + c]      = v + bl[c];
            else        g_xr1[r * 64 + c - 64] = v + br[c - 64];
        }
    }
}

// ---------------- layer1 edge pass 1: logits + segment max ----------------------
// 8 threads per edge (one per head); each head reads 8 contiguous floats (2x float4)
__global__ void edge1_logits(const int* __restrict__ ei, const float* __restrict__ att,
                             int E, int Etot) {
    int t = blockIdx.x * blockDim.x + threadIdx.x;
    int e = t >> 3, h = t & 7;
    if (e >= Etot) return;
    int src, dst;
    if (e < E) { src = ei[e]; dst = ei[E + e]; } else { src = dst = e - E; }

    const float4* pl = (const float4*)(g_xl1 + src * 64 + h * 8);
    const float4* pr = (const float4*)(g_xr1 + dst * 64 + h * 8);
    float4 a0 = pl[0], a1 = pl[1], b0 = pr[0], b1 = pr[1];
    float m[8] = {a0.x + b0.x, a0.y + b0.y, a0.z + b0.z, a0.w + b0.w,
                  a1.x + b1.x, a1.y + b1.y, a1.z + b1.z, a1.w + b1.w};
    float logit = 0.f;
#pragma unroll
    for (int c = 0; c < 8; c++) {
        float v = m[c];
        float lr = v > 0.f ? v : NEG_SLOPE * v;
        logit += lr * __ldg(att + h * 8 + c);
    }
    g_logit1[t] = logit;
    atomicMax(&g_max1[dst * 8 + h], fenc(logit));
}

// ---------------- layer1 edge pass 2: exp + segment sum -------------------------
__global__ void edge1_sum(const int* __restrict__ ei, int E, int Etot) {
    int t = blockIdx.x * blockDim.x + threadIdx.x;
    int e = t >> 3, h = t & 7;
    if (e >= Etot) return;
    int dst = (e < E) ? ei[E + e] : (e - E);
    float l = g_logit1[t];
    float mx = fdec(g_max1[dst * 8 + h]);
    atomicAdd(&g_sum1[dst * 8 + h], __expf(l - mx));
}

// ---------------- layer1 edge pass 3: alpha * xl[src] -> out[dst] ---------------
__global__ void edge1_aggr(const int* __restrict__ ei, int E, int Etot) {
    int t = blockIdx.x * blockDim.x + threadIdx.x;
    int e = t >> 3, h = t & 7;
    if (e >= Etot) return;
    int src, dst;
    if (e < E) { src = ei[e]; dst = ei[E + e]; } else { src = dst = e - E; }
    float l  = g_logit1[t];
    float mx = fdec(g_max1[dst * 8 + h]);
    float alpha = __expf(l - mx) / g_sum1[dst * 8 + h];
    const float4* pl = (const float4*)(g_xl1 + src * 64 + h * 8);
    float4 a0 = pl[0], a1 = pl[1];
    float* o = g_out1 + dst * 64 + h * 8;
    atomicAdd(o + 0, a0.x * alpha); atomicAdd(o + 1, a0.y * alpha);
    atomicAdd(o + 2, a0.z * alpha); atomicAdd(o + 3, a0.w * alpha);
    atomicAdd(o + 4, a1.x * alpha); atomicAdd(o + 5, a1.y * alpha);
    atomicAdd(o + 6, a1.z * alpha); atomicAdd(o + 7, a1.w * alpha);
}

// ---------------- GEMM2: elu(out1+bias1) [N,64] @ [64,40|40] -> g_hl2, g_hr2 ----
// block: 32 nodes, full weight (64x80) in smem, thread = (node, 10 cols)
__global__ void gemm2_kernel(const float* __restrict__ bias1,
                             const float* __restrict__ Wl2, const float* __restrict__ bl2,
                             const float* __restrict__ Wr2, const float* __restrict__ br2) {
    __shared__ float Ws[64][80];
    __shared__ float As[32][65];
    const int tid = threadIdx.x;
    const int node0 = blockIdx.x * 32;

    for (int i = tid; i < 64 * 80; i += 256) {
        int k = i / 80, c = i % 80;
        Ws[k][c] = (c < 40) ? Wl2[k * 40 + c] : Wr2[k * 40 + c - 40];
    }
    for (int i = tid; i < 32 * 64; i += 256) {
        int n = i >> 6, c = i & 63;
        int gn = node0 + n;
        float v = 0.f;
        if (gn < NN) v = g_out1[gn * 64 + c] + bias1[c];
        As[n][c] = v > 0.f ? v : (__expf(v) - 1.0f);   // ELU
    }
    __syncthreads();

    const int n = tid >> 3;        // 0..31
    const int cg = tid & 7;        // cols cg*10 .. cg*10+9
    float acc[10];
#pragma unroll
    for (int j = 0; j < 10; j++) acc[j] = 0.f;
#pragma unroll 8
    for (int k = 0; k < 64; k++) {
        float a = As[n][k];
#pragma unroll
        for (int j = 0; j < 10; j++) acc[j] += a * Ws[k][cg * 10 + j];
    }
    int gn = node0 + n;
    if (gn < NN) {
#pragma unroll
        for (int j = 0; j < 10; j++) {
            int c = cg * 10 + j;
            float v = acc[j];
            if (c < 40) g_hl2[gn * 40 + c]      = v + bl2[c];
            else        g_hr2[gn * 40 + c - 40] = v + br2[c - 40];
        }
    }
}

// ---------------- layer2 edge pass 1: logits (8 threads x 5 dims) + max ---------
__global__ void edge2_logits(const int* __restrict__ ei, const float* __restrict__ att,
                             int E, int Etot) {
    int t = blockIdx.x * blockDim.x + threadIdx.x;
    int e = t >> 3, h = t & 7;
    if (e >= Etot) return;
    int src, dst;
    if (e < E) { src = ei[e]; dst = ei[E + e]; } else { src = dst = e - E; }
    const float* pl = g_hl2 + src * 40 + h * 5;
    const float* pr = g_hr2 + dst * 40 + h * 5;
    float part = 0.f;
#pragma unroll
    for (int i = 0; i < 5; i++) {
        float v = pl[i] + pr[i];
        float lr = v > 0.f ? v : NEG_SLOPE * v;
        part += lr * __ldg(att + h * 5 + i);
    }
    part += __shfl_down_sync(0xffffffffu, part, 4, 8);
    part += __shfl_down_sync(0xffffffffu, part, 2, 8);
    part += __shfl_down_sync(0xffffffffu, part, 1, 8);
    if (h == 0) {
        g_logit2[e] = part;
        atomicMax(&g_max2[dst], fenc(part));
    }
}

// ---------------- layer2 edge pass 2: exp + sum (1 thread/edge) -----------------
__global__ void edge2_sum(const int* __restrict__ ei, int E, int Etot) {
    int e = blockIdx.x * blockDim.x + threadIdx.x;
    if (e >= Etot) return;
    int dst = (e < E) ? ei[E + e] : (e - E);
    float l = g_logit2[e];
    float mx = fdec(g_max2[dst]);
    atomicAdd(&g_sum2[dst], __expf(l - mx));
}

// ---------------- layer2 edge pass 3: aggregate ---------------------------------
__global__ void edge2_aggr(const int* __restrict__ ei, int E, int Etot) {
    int t = blockIdx.x * blockDim.x + threadIdx.x;
    int e = t >> 3, h = t & 7;
    if (e >= Etot) return;
    int src, dst;
    if (e < E) { src = ei[e]; dst = ei[E + e]; } else { src = dst = e - E; }
    float l = g_logit2[e];
    float mx = fdec(g_max2[dst]);
    float alpha = __expf(l - mx) / g_sum2[dst];
    const float* pl = g_hl2 + src * 40 + h * 5;
    float* o = g_out2 + dst * 40 + h * 5;
#pragma unroll
    for (int i = 0; i < 5; i++) atomicAdd(o + i, pl[i] * alpha);
}

// ---------------- final: out2 + bias2, log_softmax over 40 ----------------------
__global__ void final_lsm(const float* __restrict__ bias2, float* __restrict__ out) {
    int gw = (blockIdx.x * blockDim.x + threadIdx.x) >> 5;
    int lane = threadIdx.x & 31;
    if (gw >= NN) return;
    const float* row = g_out2 + gw * 40;
    float v0 = row[lane] + bias2[lane];
    float v1 = (lane < 8) ? (row[32 + lane] + bias2[32 + lane]) : -FLT_MAX;
    float m = fmaxf(v0, v1);
#pragma unroll
    for (int off = 16; off > 0; off >>= 1) m = fmaxf(m, __shfl_xor_sync(0xffffffffu, m, off));
    float s = __expf(v0 - m) + ((lane < 8) ? __expf(v1 - m) : 0.f);
#pragma unroll
    for (int off = 16; off > 0; off >>= 1) s += __shfl_xor_sync(0xffffffffu, s, off);
    float lse = m + logf(s);
    out[gw * 40 + lane] = v0 - lse;
    if (lane < 8) out[gw * 40 + 32 + lane] = v1 - lse;
}

// ---------------- launch --------------------------------------------------------
extern "C" void kernel_launch(void* const* d_in, const int* in_sizes, int n_in,
                              void* d_out, int out_size) {
    const float* x    = (const float*)d_in[0];
    const int*   ei   = (const int*)  d_in[1];
    const float* Wl1  = (const float*)d_in[2];
    const float* bl1  = (const float*)d_in[3];
    const float* Wr1  = (const float*)d_in[4];
    const float* br1  = (const float*)d_in[5];
    const float* att1 = (const float*)d_in[6];
    const float* bias1= (const float*)d_in[7];
    const float* Wl2  = (const float*)d_in[8];
    const float* bl2  = (const float*)d_in[9];
    const float* Wr2  = (const float*)d_in[10];
    const float* br2  = (const float*)d_in[11];
    const float* att2 = (const float*)d_in[12];
    const float* bias2= (const float*)d_in[13];
    float* out = (float*)d_out;

    const int E = in_sizes[1] / 2;
    const int Etot = E + NN;

    init_kernel<<<(NN * 64 + 255) / 256, 256>>>();
    gemm1_kernel<<<(NN + 63) / 64, 256>>>(x, Wl1, bl1, Wr1, br1);

    int eb8 = (Etot * 8 + 255) / 256;
    edge1_logits<<<eb8, 256>>>(ei, att1, E, Etot);
    edge1_sum   <<<eb8, 256>>>(ei, E, Etot);
    edge1_aggr  <<<eb8, 256>>>(ei, E, Etot);

    gemm2_kernel<<<(NN + 31) / 32, 256>>>(bias1, Wl2, bl2, Wr2, br2);

    edge2_logits<<<eb8, 256>>>(ei, att2, E, Etot);
    edge2_sum   <<<(Etot + 255) / 256, 256>>>(ei, E, Etot);
    edge2_aggr  <<<eb8, 256>>>(ei, E, Etot);

    final_lsm<<<(NN + 7) / 8, 256>>>(bias2, out);
}

// round 4
// speedup vs baseline: 1.7727x; 1.7727x over previous
#include <cuda_runtime.h>
#include <cuda_bf16.h>
#include <math.h>
#include <float.h>

#define NN 100000
#define IN_DIM 256
#define L1_OUT 64      // HEADS*HID
#define HEADS 8
#define HID 8
#define OUT_DIM 40
#define EMAX 1700000   // 1.6M edges + 100k self loops
#define NEG_SLOPE 0.2f

// ---------------- scratch (static __device__, no allocs allowed) ----------------
__device__ float    g_xl1[NN * L1_OUT];
__device__ float    g_xr1[NN * L1_OUT];
__device__ float    g_out1[NN * L1_OUT];
__device__ float    g_exp1[EMAX * HEADS];   // exp(logit) per (edge, head)
__device__ float    g_sum1[NN * HEADS];

__device__ float    g_hl2[NN * OUT_DIM];
__device__ float    g_hr2[NN * OUT_DIM];
__device__ float    g_exp2[EMAX];
__device__ float    g_sum2[NN];
__device__ float    g_out2[NN * OUT_DIM];

// ---------------- vectorized global reduction (intrinsic, no inline PTX) --------
__device__ __forceinline__ void red_add_v4(float* addr, float a, float b, float c, float d) {
#if __CUDA_ARCH__ >= 900
    atomicAdd((float4*)addr, make_float4(a, b, c, d));
#else
    atomicAdd(addr + 0, a); atomicAdd(addr + 1, b);
    atomicAdd(addr + 2, c); atomicAdd(addr + 3, d);
#endif
}

// ---------------- init: zero accumulators ---------------------------------------
__global__ void init_kernel() {
    int i = blockIdx.x * blockDim.x + threadIdx.x;
    if (i < NN * L1_OUT) g_out1[i] = 0.f;
    if (i < NN * OUT_DIM) g_out2[i] = 0.f;
    if (i < NN * HEADS) g_sum1[i] = 0.f;
    if (i < NN)         g_sum2[i] = 0.f;
}

// ---------------- GEMM1: [N,256] @ [256,64|64] -> g_xl1, g_xr1 -------------------
__global__ void gemm1_kernel(const float* __restrict__ x,
                             const float* __restrict__ Wl, const float* __restrict__ bl,
                             const float* __restrict__ Wr, const float* __restrict__ br) {
    __shared__ float As[16][64];
    __shared__ float Bs[16][128];
    const int tid = threadIdx.x;
    const int block_row = blockIdx.x * 64;
    const int tx = tid & 31;
    const int ty = tid >> 5;

    float acc[8][4];
#pragma unroll
    for (int i = 0; i < 8; i++)
#pragma unroll
        for (int j = 0; j < 4; j++) acc[i][j] = 0.f;

    const int ar = tid >> 2;
    const int ak = (tid & 3) * 4;
    const int kr = tid >> 4;
    const int bc = (tid & 15) * 8;

    for (int k0 = 0; k0 < IN_DIM; k0 += 16) {
        int gr = block_row + ar;
        float4 av = make_float4(0.f, 0.f, 0.f, 0.f);
        if (gr < NN) av = *(const float4*)(x + (long)gr * IN_DIM + k0 + ak);
        As[ak + 0][ar] = av.x; As[ak + 1][ar] = av.y;
        As[ak + 2][ar] = av.z; As[ak + 3][ar] = av.w;

        const float* Bsrc = (bc < 64) ? (Wl + (k0 + kr) * 64 + bc)
                                      : (Wr + (k0 + kr) * 64 + bc - 64);
        float4 b0 = *(const float4*)(Bsrc);
        float4 b1 = *(const float4*)(Bsrc + 4);
        *(float4*)&Bs[kr][bc] = b0;
        *(float4*)&Bs[kr][bc + 4] = b1;
        __syncthreads();

#pragma unroll
        for (int kk = 0; kk < 16; kk++) {
            float4 a0 = *(float4*)&As[kk][ty * 8];
            float4 a1 = *(float4*)&As[kk][ty * 8 + 4];
            float4 b  = *(float4*)&Bs[kk][tx * 4];
            float ra[8] = {a0.x, a0.y, a0.z, a0.w, a1.x, a1.y, a1.z, a1.w};
            float rb[4] = {b.x, b.y, b.z, b.w};
#pragma unroll
            for (int i = 0; i < 8; i++)
#pragma unroll
                for (int j = 0; j < 4; j++) acc[i][j] += ra[i] * rb[j];
        }
        __syncthreads();
    }

#pragma unroll
    for (int i = 0; i < 8; i++) {
        int r = block_row + ty * 8 + i;
        if (r >= NN) continue;
#pragma unroll
        for (int j = 0; j < 4; j++) {
            int c = tx * 4 + j;
            float v = acc[i][j];
            if (c < 64) g_xl1[r * 64 + c]      = v + bl[c];
            else        g_xr1[r * 64 + c - 64] = v + br[c - 64];
        }
    }
}

// ---------------- layer1 pass A: exp(logit) + segment sum -----------------------
// 8 threads per edge (one per head). No max subtraction: logits are O(1), exp-safe.
__global__ void edge1_logits(const int* __restrict__ ei, const float* __restrict__ att,
                             int E, int Etot) {
    int t = blockIdx.x * blockDim.x + threadIdx.x;
    int e = t >> 3, h = t & 7;
    if (e >= Etot) return;
    int src, dst;
    if (e < E) { src = ei[e]; dst = ei[E + e]; } else { src = dst = e - E; }

    const float4* pl = (const float4*)(g_xl1 + src * 64 + h * 8);
    const float4* pr = (const float4*)(g_xr1 + dst * 64 + h * 8);
    float4 a0 = pl[0], a1 = pl[1], b0 = pr[0], b1 = pr[1];
    float m[8] = {a0.x + b0.x, a0.y + b0.y, a0.z + b0.z, a0.w + b0.w,
                  a1.x + b1.x, a1.y + b1.y, a1.z + b1.z, a1.w + b1.w};
    float logit = 0.f;
#pragma unroll
    for (int c = 0; c < 8; c++) {
        float v = m[c];
        float lr = v > 0.f ? v : NEG_SLOPE * v;
        logit += lr * __ldg(att + h * 8 + c);
    }
    float ev = __expf(logit);
    g_exp1[t] = ev;
    atomicAdd(&g_sum1[dst * 8 + h], ev);
}

// ---------------- layer1 pass B: alpha * xl[src] -> out[dst] (v4 red) -----------
__global__ void edge1_aggr(const int* __restrict__ ei, int E, int Etot) {
    int t = blockIdx.x * blockDim.x + threadIdx.x;
    int e = t >> 3, h = t & 7;
    if (e >= Etot) return;
    int src, dst;
    if (e < E) { src = ei[e]; dst = ei[E + e]; } else { src = dst = e - E; }
    float alpha = g_exp1[t] / g_sum1[dst * 8 + h];
    const float4* pl = (const float4*)(g_xl1 + src * 64 + h * 8);
    float4 a0 = pl[0], a1 = pl[1];
    float* o = g_out1 + dst * 64 + h * 8;
    red_add_v4(o,     a0.x * alpha, a0.y * alpha, a0.z * alpha, a0.w * alpha);
    red_add_v4(o + 4, a1.x * alpha, a1.y * alpha, a1.z * alpha, a1.w * alpha);
}

// ---------------- GEMM2: elu(out1+bias1) [N,64] @ [64,40|40] -> g_hl2, g_hr2 ----
__global__ void gemm2_kernel(const float* __restrict__ bias1,
                             const float* __restrict__ Wl2, const float* __restrict__ bl2,
                             const float* __restrict__ Wr2, const float* __restrict__ br2) {
    __shared__ float Ws[64][80];
    __shared__ float As[32][65];
    const int tid = threadIdx.x;
    const int node0 = blockIdx.x * 32;

    for (int i = tid; i < 64 * 80; i += 256) {
        int k = i / 80, c = i % 80;
        Ws[k][c] = (c < 40) ? Wl2[k * 40 + c] : Wr2[k * 40 + c - 40];
    }
    for (int i = tid; i < 32 * 64; i += 256) {
        int n = i >> 6, c = i & 63;
        int gn = node0 + n;
        float v = 0.f;
        if (gn < NN) v = g_out1[gn * 64 + c] + bias1[c];
        As[n][c] = v > 0.f ? v : (__expf(v) - 1.0f);   // ELU
    }
    __syncthreads();

    const int n = tid >> 3;
    const int cg = tid & 7;
    float acc[10];
#pragma unroll
    for (int j = 0; j < 10; j++) acc[j] = 0.f;
#pragma unroll 8
    for (int k = 0; k < 64; k++) {
        float a = As[n][k];
#pragma unroll
        for (int j = 0; j < 10; j++) acc[j] += a * Ws[k][cg * 10 + j];
    }
    int gn = node0 + n;
    if (gn < NN) {
#pragma unroll
        for (int j = 0; j < 10; j++) {
            int c = cg * 10 + j;
            float v = acc[j];
            if (c < 40) g_hl2[gn * 40 + c]      = v + bl2[c];
            else        g_hr2[gn * 40 + c - 40] = v + br2[c - 40];
        }
    }
}

// ---------------- layer2 pass A: exp(logit) + sum (8 threads/edge, shfl) --------
__global__ void edge2_logits(const int* __restrict__ ei, const float* __restrict__ att,
                             int E, int Etot) {
    int t = blockIdx.x * blockDim.x + threadIdx.x;
    int e = t >> 3, h = t & 7;
    if (e >= Etot) return;
    int src, dst;
    if (e < E) { src = ei[e]; dst = ei[E + e]; } else { src = dst = e - E; }
    const float* pl = g_hl2 + src * 40 + h * 5;
    const float* pr = g_hr2 + dst * 40 + h * 5;
    float part = 0.f;
#pragma unroll
    for (int i = 0; i < 5; i++) {
        float v = pl[i] + pr[i];
        float lr = v > 0.f ? v : NEG_SLOPE * v;
        part += lr * __ldg(att + h * 5 + i);
    }
    part += __shfl_down_sync(0xffffffffu, part, 4, 8);
    part += __shfl_down_sync(0xffffffffu, part, 2, 8);
    part += __shfl_down_sync(0xffffffffu, part, 1, 8);
    if (h == 0) {
        float ev = __expf(part);
        g_exp2[e] = ev;
        atomicAdd(&g_sum2[dst], ev);
    }
}

// ---------------- layer2 pass B: aggregate (10 threads/edge, aligned v4 red) ----
__global__ void edge2_aggr(const int* __restrict__ ei, int E, int Etot) {
    int t = blockIdx.x * blockDim.x + threadIdx.x;
    int e = t / 10, q = t % 10;
    if (e >= Etot) return;
    int src, dst;
    if (e < E) { src = ei[e]; dst = ei[E + e]; } else { src = dst = e - E; }
    float alpha = g_exp2[e] / g_sum2[dst];
    const float4* pl = (const float4*)(g_hl2 + src * 40) + q;
    float4 a = *pl;
    float* o = g_out2 + dst * 40 + q * 4;
    red_add_v4(o, a.x * alpha, a.y * alpha, a.z * alpha, a.w * alpha);
}

// ---------------- final: out2 + bias2, log_softmax over 40 ----------------------
__global__ void final_lsm(const float* __restrict__ bias2, float* __restrict__ out) {
    int gw = (blockIdx.x * blockDim.x + threadIdx.x) >> 5;
    int lane = threadIdx.x & 31;
    if (gw >= NN) return;
    const float* row = g_out2 + gw * 40;
    float v0 = row[lane] + bias2[lane];
    float v1 = (lane < 8) ? (row[32 + lane] + bias2[32 + lane]) : -FLT_MAX;
    float m = fmaxf(v0, v1);
#pragma unroll
    for (int off = 16; off > 0; off >>= 1) m = fmaxf(m, __shfl_xor_sync(0xffffffffu, m, off));
    float s = __expf(v0 - m) + ((lane < 8) ? __expf(v1 - m) : 0.f);
#pragma unroll
    for (int off = 16; off > 0; off >>= 1) s += __shfl_xor_sync(0xffffffffu, s, off);
    float lse = m + logf(s);
    out[gw * 40 + lane] = v0 - lse;
    if (lane < 8) out[gw * 40 + 32 + lane] = v1 - lse;
}

// ---------------- launch --------------------------------------------------------
extern "C" void kernel_launch(void* const* d_in, const int* in_sizes, int n_in,
                              void* d_out, int out_size) {
    const float* x    = (const float*)d_in[0];
    const int*   ei   = (const int*)  d_in[1];
    const float* Wl1  = (const float*)d_in[2];
    const float* bl1  = (const float*)d_in[3];
    const float* Wr1  = (const float*)d_in[4];
    const float* br1  = (const float*)d_in[5];
    const float* att1 = (const float*)d_in[6];
    const float* bias1= (const float*)d_in[7];
    const float* Wl2  = (const float*)d_in[8];
    const float* bl2  = (const float*)d_in[9];
    const float* Wr2  = (const float*)d_in[10];
    const float* br2  = (const float*)d_in[11];
    const float* att2 = (const float*)d_in[12];
    const float* bias2= (const float*)d_in[13];
    float* out = (float*)d_out;

    const int E = in_sizes[1] / 2;
    const int Etot = E + NN;

    init_kernel<<<(NN * 64 + 255) / 256, 256>>>();
    gemm1_kernel<<<(NN + 63) / 64, 256>>>(x, Wl1, bl1, Wr1, br1);

    int eb8 = (Etot * 8 + 255) / 256;
    edge1_logits<<<eb8, 256>>>(ei, att1, E, Etot);
    edge1_aggr  <<<eb8, 256>>>(ei, E, Etot);

    gemm2_kernel<<<(NN + 31) / 32, 256>>>(bias1, Wl2, bl2, Wr2, br2);

    edge2_logits<<<eb8, 256>>>(ei, att2, E, Etot);
    int eb10 = (Etot * 10 + 255) / 256;
    edge2_aggr  <<<eb10, 256>>>(ei, E, Etot);

    final_lsm<<<(NN + 7) / 8, 256>>>(bias2, out);
}

// round 5
// speedup vs baseline: 2.3779x; 1.3414x over previous
#include <cuda_runtime.h>
#include <cuda_bf16.h>
#include <math.h>
#include <float.h>

#define NN 100000
#define IN_DIM 256
#define L1_OUT 64      // HEADS*HID
#define HEADS 8
#define HID 8
#define OUT_DIM 40
#define EMAX 1700000   // 1.6M edges + 100k self loops
#define NEG_SLOPE 0.2f
#define SCAN_B 1024

// ---------------- scratch (static __device__, no allocs allowed) ----------------
__device__ float g_xl1[NN * L1_OUT];
__device__ float g_xr1[NN * L1_OUT];
__device__ float g_out1[NN * L1_OUT];
__device__ float g_hl2[NN * OUT_DIM];
__device__ float g_hr2[NN * OUT_DIM];
__device__ float g_out2[NN * OUT_DIM];

__device__ int g_cnt[NN];        // per-dst degree (incl self loop)
__device__ int g_incl[NN];       // inclusive scan scratch
__device__ int g_blksum[128];
__device__ int g_offs[NN + 1];   // exclusive offsets
__device__ int g_cursor[NN];     // scatter cursors
__device__ int g_csr_src[EMAX];  // src node per CSR slot

// ---------------- CSR build ------------------------------------------------------
__global__ void csr_init() {
    int i = blockIdx.x * blockDim.x + threadIdx.x;
    if (i < NN) g_cnt[i] = 1;    // self loop
}

__global__ void csr_hist(const int* __restrict__ ei, int E) {
    int e = blockIdx.x * blockDim.x + threadIdx.x;
    if (e < E) atomicAdd(&g_cnt[ei[E + e]], 1);
}

__global__ void scan1() {
    __shared__ int sm[SCAN_B];
    int i = blockIdx.x * SCAN_B + threadIdx.x;
    int v = (i < NN) ? g_cnt[i] : 0;
    sm[threadIdx.x] = v;
    __syncthreads();
    for (int off = 1; off < SCAN_B; off <<= 1) {
        int t = (threadIdx.x >= off) ? sm[threadIdx.x - off] : 0;
        __syncthreads();
        sm[threadIdx.x] += t;
        __syncthreads();
    }
    if (i < NN) g_incl[i] = sm[threadIdx.x];
    if (threadIdx.x == SCAN_B - 1) g_blksum[blockIdx.x] = sm[threadIdx.x];
}

__global__ void scan2(int nb) {
    __shared__ int sm[128];
    int v = (threadIdx.x < nb) ? g_blksum[threadIdx.x] : 0;
    sm[threadIdx.x] = v;
    __syncthreads();
    for (int off = 1; off < 128; off <<= 1) {
        int t = (threadIdx.x >= off) ? sm[threadIdx.x - off] : 0;
        __syncthreads();
        sm[threadIdx.x] += t;
        __syncthreads();
    }
    if (threadIdx.x < nb) g_blksum[threadIdx.x] = sm[threadIdx.x];
}

__global__ void scan3() {
    int i = blockIdx.x * 256 + threadIdx.x;
    if (i >= NN) return;
    int blk = i / SCAN_B;
    int add = (blk > 0) ? g_blksum[blk - 1] : 0;
    int tot = g_incl[i] + add;          // inclusive
    g_offs[i + 1] = tot;
    g_cursor[i] = tot - g_cnt[i];       // exclusive start
    if (i == 0) g_offs[0] = 0;
}

__global__ void csr_scatter(const int* __restrict__ ei, int E, int Etot) {
    int e = blockIdx.x * blockDim.x + threadIdx.x;
    if (e >= Etot) return;
    int src, dst;
    if (e < E) { src = ei[e]; dst = ei[E + e]; } else { src = dst = e - E; }
    int pos = atomicAdd(&g_cursor[dst], 1);
    g_csr_src[pos] = src;
}

// ---------------- GEMM1: [N,256] @ [256,64|64] -> g_xl1, g_xr1 -------------------
__global__ void gemm1_kernel(const float* __restrict__ x,
                             const float* __restrict__ Wl, const float* __restrict__ bl,
                             const float* __restrict__ Wr, const float* __restrict__ br) {
    __shared__ float As[16][64];
    __shared__ float Bs[16][128];
    const int tid = threadIdx.x;
    const int block_row = blockIdx.x * 64;
    const int tx = tid & 31;
    const int ty = tid >> 5;

    float acc[8][4];
#pragma unroll
    for (int i = 0; i < 8; i++)
#pragma unroll
        for (int j = 0; j < 4; j++) acc[i][j] = 0.f;

    const int ar = tid >> 2;
    const int ak = (tid & 3) * 4;
    const int kr = tid >> 4;
    const int bc = (tid & 15) * 8;

    for (int k0 = 0; k0 < IN_DIM; k0 += 16) {
        int gr = block_row + ar;
        float4 av = make_float4(0.f, 0.f, 0.f, 0.f);
        if (gr < NN) av = *(const float4*)(x + (long)gr * IN_DIM + k0 + ak);
        As[ak + 0][ar] = av.x; As[ak + 1][ar] = av.y;
        As[ak + 2][ar] = av.z; As[ak + 3][ar] = av.w;

        const float* Bsrc = (bc < 64) ? (Wl + (k0 + kr) * 64 + bc)
                                      : (Wr + (k0 + kr) * 64 + bc - 64);
        float4 b0 = *(const float4*)(Bsrc);
        float4 b1 = *(const float4*)(Bsrc + 4);
        *(float4*)&Bs[kr][bc] = b0;
        *(float4*)&Bs[kr][bc + 4] = b1;
        __syncthreads();

#pragma unroll
        for (int kk = 0; kk < 16; kk++) {
            float4 a0 = *(float4*)&As[kk][ty * 8];
            float4 a1 = *(float4*)&As[kk][ty * 8 + 4];
            float4 b  = *(float4*)&Bs[kk][tx * 4];
            float ra[8] = {a0.x, a0.y, a0.z, a0.w, a1.x, a1.y, a1.z, a1.w};
            float rb[4] = {b.x, b.y, b.z, b.w};
#pragma unroll
            for (int i = 0; i < 8; i++)
#pragma unroll
                for (int j = 0; j < 4; j++) acc[i][j] += ra[i] * rb[j];
        }
        __syncthreads();
    }

#pragma unroll
    for (int i = 0; i < 8; i++) {
        int r = block_row + ty * 8 + i;
        if (r >= NN) continue;
#pragma unroll
        for (int j = 0; j < 4; j++) {
            int c = tx * 4 + j;
            float v = acc[i][j];
            if (c < 64) g_xl1[r * 64 + c]      = v + bl[c];
            else        g_xr1[r * 64 + c - 64] = v + br[c - 64];
        }
    }
}

// ---------------- layer1 fused: softmax-weighted aggregation, warp per dst ------
// lane handles dims 2*lane, 2*lane+1; head = lane/4; no atomics, no exp storage.
__global__ void l1_fused(const float* __restrict__ att) {
    int w = (blockIdx.x * blockDim.x + threadIdx.x) >> 5;
    int lane = threadIdx.x & 31;
    if (w >= NN) return;
    const int dst = w;
    const int beg = g_offs[dst], end = g_offs[dst + 1];

    float2 xr = *(const float2*)(g_xr1 + dst * 64 + lane * 2);
    float a0 = __ldg(att + lane * 2);
    float a1 = __ldg(att + lane * 2 + 1);

    float acc0 = 0.f, acc1 = 0.f, s = 0.f;

    for (int base = beg; base < end; base += 32) {
        int mysrc = (base + lane < end) ? g_csr_src[base + lane] : 0;
        int cnt = min(32, end - base);

        // depth-2 software pipeline on the xl gather
        int src_n = __shfl_sync(0xffffffffu, mysrc, 0);
        float2 xl_n = *(const float2*)(g_xl1 + src_n * 64 + lane * 2);
        for (int j = 0; j < cnt; j++) {
            float2 xl = xl_n;
            if (j + 1 < cnt) {
                int sj = __shfl_sync(0xffffffffu, mysrc, j + 1);
                xl_n = *(const float2*)(g_xl1 + sj * 64 + lane * 2);
            }
            float m0 = xl.x + xr.x, m1 = xl.y + xr.y;
            float l0 = m0 > 0.f ? m0 : NEG_SLOPE * m0;
            float l1 = m1 > 0.f ? m1 : NEG_SLOPE * m1;
            float p = l0 * a0 + l1 * a1;
            p += __shfl_xor_sync(0xffffffffu, p, 1);
            p += __shfl_xor_sync(0xffffffffu, p, 2);   // per-head logit in 4-lane group
            float ev = __expf(p);
            acc0 += ev * xl.x; acc1 += ev * xl.y; s += ev;
        }
    }
    float inv = 1.f / s;   // s identical across the 4 lanes of a head
    *(float2*)(g_out1 + dst * 64 + lane * 2) = make_float2(acc0 * inv, acc1 * inv);
}

// ---------------- GEMM2: elu(out1+bias1) [N,64] @ [64,40|40] -> g_hl2, g_hr2 ----
__global__ void gemm2_kernel(const float* __restrict__ bias1,
                             const float* __restrict__ Wl2, const float* __restrict__ bl2,
                             const float* __restrict__ Wr2, const float* __restrict__ br2) {
    __shared__ float Ws[64][80];
    __shared__ float As[32][65];
    const int tid = threadIdx.x;
    const int node0 = blockIdx.x * 32;

    for (int i = tid; i < 64 * 80; i += 256) {
        int k = i / 80, c = i % 80;
        Ws[k][c] = (c < 40) ? Wl2[k * 40 + c] : Wr2[k * 40 + c - 40];
    }
    for (int i = tid; i < 32 * 64; i += 256) {
        int n = i >> 6, c = i & 63;
        int gn = node0 + n;
        float v = 0.f;
        if (gn < NN) v = g_out1[gn * 64 + c] + bias1[c];
        As[n][c] = v > 0.f ? v : (__expf(v) - 1.0f);   // ELU
    }
    __syncthreads();

    const int n = tid >> 3;
    const int cg = tid & 7;
    float acc[10];
#pragma unroll
    for (int j = 0; j < 10; j++) acc[j] = 0.f;
#pragma unroll 8
    for (int k = 0; k < 64; k++) {
        float a = As[n][k];
#pragma unroll
        for (int j = 0; j < 10; j++) acc[j] += a * Ws[k][cg * 10 + j];
    }
    int gn = node0 + n;
    if (gn < NN) {
#pragma unroll
        for (int j = 0; j < 10; j++) {
            int c = cg * 10 + j;
            float v = acc[j];
            if (c < 40) g_hl2[gn * 40 + c]      = v + bl2[c];
            else        g_hr2[gn * 40 + c - 40] = v + br2[c - 40];
        }
    }
}

// ---------------- layer2 fused: warp per dst, 20 active lanes x float2 ----------
__global__ void l2_fused(const float* __restrict__ att) {
    int w = (blockIdx.x * blockDim.x + threadIdx.x) >> 5;
    int lane = threadIdx.x & 31;
    if (w >= NN) return;
    const int dst = w;
    const int beg = g_offs[dst], end = g_offs[dst + 1];
    const bool act = lane < 20;

    float2 hr = act ? *(const float2*)(g_hr2 + dst * 40 + lane * 2)
                    : make_float2(0.f, 0.f);
    float a0 = act ? __ldg(att + lane * 2)     : 0.f;
    float a1 = act ? __ldg(att + lane * 2 + 1) : 0.f;

    float acc0 = 0.f, acc1 = 0.f, s = 0.f;

    for (int base = beg; base < end; base += 32) {
        int mysrc = (base + lane < end) ? g_csr_src[base + lane] : 0;
        int cnt = min(32, end - base);

        int src_n = __shfl_sync(0xffffffffu, mysrc, 0);
        float2 hl_n = act ? *(const float2*)(g_hl2 + src_n * 40 + lane * 2)
                          : make_float2(0.f, 0.f);
        for (int j = 0; j < cnt; j++) {
            float2 hl = hl_n;
            if (j + 1 < cnt) {
                int sj = __shfl_sync(0xffffffffu, mysrc, j + 1);
                if (act) hl_n = *(const float2*)(g_hl2 + sj * 40 + lane * 2);
            }
            float m0 = hl.x + hr.x, m1 = hl.y + hr.y;
            float l0 = m0 > 0.f ? m0 : NEG_SLOPE * m0;
            float l1 = m1 > 0.f ? m1 : NEG_SLOPE * m1;
            float p = l0 * a0 + l1 * a1;   // 0 for inactive lanes
#pragma unroll
            for (int off = 16; off > 0; off >>= 1)
                p += __shfl_xor_sync(0xffffffffu, p, off);   // full-warp logit
            float ev = __expf(p);
            acc0 += ev * hl.x; acc1 += ev * hl.y; s += ev;
        }
    }
    float inv = 1.f / s;
    if (act)
        *(float2*)(g_out2 + dst * 40 + lane * 2) = make_float2(acc0 * inv, acc1 * inv);
}

// ---------------- final: out2 + bias2, log_softmax over 40 ----------------------
__global__ void final_lsm(const float* __restrict__ bias2, float* __restrict__ out) {
    int gw = (blockIdx.x * blockDim.x + threadIdx.x) >> 5;
    int lane = threadIdx.x & 31;
    if (gw >= NN) return;
    const float* row = g_out2 + gw * 40;
    float v0 = row[lane] + bias2[lane];
    float v1 = (lane < 8) ? (row[32 + lane] + bias2[32 + lane]) : -FLT_MAX;
    float m = fmaxf(v0, v1);
#pragma unroll
    for (int off = 16; off > 0; off >>= 1) m = fmaxf(m, __shfl_xor_sync(0xffffffffu, m, off));
    float s = __expf(v0 - m) + ((lane < 8) ? __expf(v1 - m) : 0.f);
#pragma unroll
    for (int off = 16; off > 0; off >>= 1) s += __shfl_xor_sync(0xffffffffu, s, off);
    float lse = m + logf(s);
    out[gw * 40 + lane] = v0 - lse;
    if (lane < 8) out[gw * 40 + 32 + lane] = v1 - lse;
}

// ---------------- launch --------------------------------------------------------
extern "C" void kernel_launch(void* const* d_in, const int* in_sizes, int n_in,
                              void* d_out, int out_size) {
    const float* x    = (const float*)d_in[0];
    const int*   ei   = (const int*)  d_in[1];
    const float* Wl1  = (const float*)d_in[2];
    const float* bl1  = (const float*)d_in[3];
    const float* Wr1  = (const float*)d_in[4];
    const float* br1  = (const float*)d_in[5];
    const float* att1 = (const float*)d_in[6];
    const float* bias1= (const float*)d_in[7];
    const float* Wl2  = (const float*)d_in[8];
    const float* bl2  = (const float*)d_in[9];
    const float* Wr2  = (const float*)d_in[10];
    const float* br2  = (const float*)d_in[11];
    const float* att2 = (const float*)d_in[12];
    const float* bias2= (const float*)d_in[13];
    float* out = (float*)d_out;

    const int E = in_sizes[1] / 2;
    const int Etot = E + NN;
    const int nb = (NN + SCAN_B - 1) / SCAN_B;

    // CSR build (shared by both layers)
    csr_init<<<(NN + 255) / 256, 256>>>();
    csr_hist<<<(E + 255) / 256, 256>>>(ei, E);
    scan1<<<nb, SCAN_B>>>();
    scan2<<<1, 128>>>(nb);
    scan3<<<(NN + 255) / 256, 256>>>();
    csr_scatter<<<(Etot + 255) / 256, 256>>>(ei, E, Etot);

    gemm1_kernel<<<(NN + 63) / 64, 256>>>(x, Wl1, bl1, Wr1, br1);
    l1_fused<<<(NN * 32 + 255) / 256, 256>>>(att1);
    gemm2_kernel<<<(NN + 31) / 32, 256>>>(bias1, Wl2, bl2, Wr2, br2);
    l2_fused<<<(NN * 32 + 255) / 256, 256>>>(att2);
    final_lsm<<<(NN + 7) / 8, 256>>>(bias2, out);
}

// round 6
// speedup vs baseline: 2.4350x; 1.0240x over previous
#include <cuda_runtime.h>
#include <cuda_bf16.h>
#include <mma.h>
#include <math.h>
#include <float.h>

using namespace nvcuda;

#define NN 100000
#define NPAD 100096    // NN rounded up to 128 (gemm1 tile M)
#define IN_DIM 256
#define L1_OUT 64      // HEADS*HID
#define HEADS 8
#define HID 8
#define OUT_DIM 40
#define EMAX 1700000   // 1.6M edges + 100k self loops
#define NEG_SLOPE 0.2f
#define SCAN_B 1024

// ---------------- scratch (static __device__, no allocs allowed) ----------------
__device__ float g_xl1[NPAD * L1_OUT];   // padded: gemm1 stores full tiles unguarded
__device__ float g_xr1[NPAD * L1_OUT];
__device__ float g_out1[NN * L1_OUT];
__device__ float g_hl2[NN * OUT_DIM];
__device__ float g_hr2[NN * OUT_DIM];
__device__ float g_out2[NN * OUT_DIM];

__device__ int g_cnt[NN];
__device__ int g_incl[NN];
__device__ int g_blksum[128];
__device__ int g_offs[NN + 1];
__device__ int g_cursor[NN];
__device__ int g_csr_src[EMAX];

// ---------------- CSR build ------------------------------------------------------
__global__ void csr_init() {
    int i = blockIdx.x * blockDim.x + threadIdx.x;
    if (i < NN) g_cnt[i] = 1;    // self loop
}

__global__ void csr_hist(const int* __restrict__ ei, int E) {
    int e = blockIdx.x * blockDim.x + threadIdx.x;
    if (e < E) atomicAdd(&g_cnt[ei[E + e]], 1);
}

__global__ void scan1() {
    __shared__ int sm[SCAN_B];
    int i = blockIdx.x * SCAN_B + threadIdx.x;
    int v = (i < NN) ? g_cnt[i] : 0;
    sm[threadIdx.x] = v;
    __syncthreads();
    for (int off = 1; off < SCAN_B; off <<= 1) {
        int t = (threadIdx.x >= off) ? sm[threadIdx.x - off] : 0;
        __syncthreads();
        sm[threadIdx.x] += t;
        __syncthreads();
    }
    if (i < NN) g_incl[i] = sm[threadIdx.x];
    if (threadIdx.x == SCAN_B - 1) g_blksum[blockIdx.x] = sm[threadIdx.x];
}

__global__ void scan2(int nb) {
    __shared__ int sm[128];
    int v = (threadIdx.x < nb) ? g_blksum[threadIdx.x] : 0;
    sm[threadIdx.x] = v;
    __syncthreads();
    for (int off = 1; off < 128; off <<= 1) {
        int t = (threadIdx.x >= off) ? sm[threadIdx.x - off] : 0;
        __syncthreads();
        sm[threadIdx.x] += t;
        __syncthreads();
    }
    if (threadIdx.x < nb) g_blksum[threadIdx.x] = sm[threadIdx.x];
}

__global__ void scan3() {
    int i = blockIdx.x * 256 + threadIdx.x;
    if (i >= NN) return;
    int blk = i / SCAN_B;
    int add = (blk > 0) ? g_blksum[blk - 1] : 0;
    int tot = g_incl[i] + add;
    g_offs[i + 1] = tot;
    g_cursor[i] = tot - g_cnt[i];
    if (i == 0) g_offs[0] = 0;
}

__global__ void csr_scatter(const int* __restrict__ ei, int E, int Etot) {
    int e = blockIdx.x * blockDim.x + threadIdx.x;
    if (e >= Etot) return;
    int src, dst;
    if (e < E) { src = ei[e]; dst = ei[E + e]; } else { src = dst = e - E; }
    int pos = atomicAdd(&g_cursor[dst], 1);
    g_csr_src[pos] = src;
}

// ---------------- GEMM1 (tf32 tensor cores): X[N,256] @ [Wl|Wr] -> xl1|xr1 -------
// Block 128x128x32, 8 warps (4x2), warp tile 32x64 = 2x4 wmma m16n16k8 tiles.
// No bias here (folded into l1_fused). Padded outputs -> unguarded tile stores.
#define ASTRIDE 40     // 32 + 8 pad: fragment-lane banks (8r+c)%32 conflict-free
#define BSTRIDE 136    // 128 + 8 pad

__global__ void gemm1_tc(const float* __restrict__ x,
                         const float* __restrict__ Wl,
                         const float* __restrict__ Wr) {
    __shared__ float As[128][ASTRIDE];
    __shared__ float Bs[32][BSTRIDE];
    const int tid = threadIdx.x;
    const int w = tid >> 5;
    const int warp_m = w & 3;        // rows warp_m*32
    const int warp_n = w >> 2;       // cols warp_n*64 (0 -> xl, 1 -> xr)
    const int block_row = blockIdx.x * 128;

    wmma::fragment<wmma::accumulator, 16, 16, 8, float> acc[2][4];
#pragma unroll
    for (int mt = 0; mt < 2; mt++)
#pragma unroll
        for (int nt = 0; nt < 4; nt++) wmma::fill_fragment(acc[mt][nt], 0.f);

    for (int k0 = 0; k0 < IN_DIM; k0 += 32) {
        // A tile: 128 rows x 32 cols = 1024 float4, 4 per thread
#pragma unroll
        for (int i = 0; i < 4; i++) {
            int f = tid + i * 256;
            int r = f >> 3, c = (f & 7) * 4;
            int gr = block_row + r;
            float4 v = make_float4(0.f, 0.f, 0.f, 0.f);
            if (gr < NN) v = *(const float4*)(x + (size_t)gr * IN_DIM + k0 + c);
            As[r][c + 0] = wmma::__float_to_tf32(v.x);
            As[r][c + 1] = wmma::__float_to_tf32(v.y);
            As[r][c + 2] = wmma::__float_to_tf32(v.z);
            As[r][c + 3] = wmma::__float_to_tf32(v.w);
        }
        // B tile: 32 rows(k) x 128 cols = 1024 float4, 4 per thread
#pragma unroll
        for (int i = 0; i < 4; i++) {
            int f = tid + i * 256;
            int r = f >> 5, c = (f & 31) * 4;
            const float* src = (c < 64) ? (Wl + (size_t)(k0 + r) * 64 + c)
                                        : (Wr + (size_t)(k0 + r) * 64 + c - 64);
            float4 v = *(const float4*)src;
            Bs[r][c + 0] = wmma::__float_to_tf32(v.x);
            Bs[r][c + 1] = wmma::__float_to_tf32(v.y);
            Bs[r][c + 2] = wmma::__float_to_tf32(v.z);
            Bs[r][c + 3] = wmma::__float_to_tf32(v.w);
        }
        __syncthreads();

#pragma unroll
        for (int kk = 0; kk < 32; kk += 8) {
            wmma::fragment<wmma::matrix_a, 16, 16, 8, wmma::precision::tf32, wmma::row_major> af[2];
            wmma::fragment<wmma::matrix_b, 16, 16, 8, wmma::precision::tf32, wmma::row_major> bf[4];
#pragma unroll
            for (int mt = 0; mt < 2; mt++)
                wmma::load_matrix_sync(af[mt], &As[warp_m * 32 + mt * 16][kk], ASTRIDE);
#pragma unroll
            for (int nt = 0; nt < 4; nt++)
                wmma::load_matrix_sync(bf[nt], &Bs[kk][warp_n * 64 + nt * 16], BSTRIDE);
#pragma unroll
            for (int mt = 0; mt < 2; mt++)
#pragma unroll
                for (int nt = 0; nt < 4; nt++)
                    wmma::mma_sync(acc[mt][nt], af[mt], bf[nt], acc[mt][nt]);
        }
        __syncthreads();
    }

    // epilogue: direct tile stores into padded outputs
#pragma unroll
    for (int mt = 0; mt < 2; mt++) {
        int r0 = block_row + warp_m * 32 + mt * 16;
#pragma unroll
        for (int nt = 0; nt < 4; nt++) {
            int c0 = warp_n * 64 + nt * 16;
            float* dst = (c0 < 64) ? (g_xl1 + (size_t)r0 * 64 + c0)
                                   : (g_xr1 + (size_t)r0 * 64 + c0 - 64);
            wmma::store_matrix_sync(dst, acc[mt][nt], 64, wmma::mem_row_major);
        }
    }
}

// ---------------- layer1 fused: softmax-weighted aggregation, warp per dst ------
// lane = 2 feature dims; head = lane/4. Biases bl/br folded in here.
__global__ void l1_fused(const float* __restrict__ att,
                         const float* __restrict__ bl, const float* __restrict__ br) {
    int w = (blockIdx.x * blockDim.x + threadIdx.x) >> 5;
    int lane = threadIdx.x & 31;
    if (w >= NN) return;
    const int dst = w;
    const int beg = g_offs[dst], end = g_offs[dst + 1];

    float bl0 = __ldg(bl + lane * 2), bl1 = __ldg(bl + lane * 2 + 1);
    float2 xr = *(const float2*)(g_xr1 + dst * 64 + lane * 2);
    xr.x += __ldg(br + lane * 2); xr.y += __ldg(br + lane * 2 + 1);
    float a0 = __ldg(att + lane * 2);
    float a1 = __ldg(att + lane * 2 + 1);

    float acc0 = 0.f, acc1 = 0.f, s = 0.f;

    for (int base = beg; base < end; base += 32) {
        int mysrc = (base + lane < end) ? g_csr_src[base + lane] : 0;
        int cnt = min(32, end - base);

        int src_n = __shfl_sync(0xffffffffu, mysrc, 0);
        float2 xl_n = *(const float2*)(g_xl1 + src_n * 64 + lane * 2);
        for (int j = 0; j < cnt; j++) {
            float2 xl = xl_n;
            if (j + 1 < cnt) {
                int sj = __shfl_sync(0xffffffffu, mysrc, j + 1);
                xl_n = *(const float2*)(g_xl1 + sj * 64 + lane * 2);
            }
            xl.x += bl0; xl.y += bl1;
            float m0 = xl.x + xr.x, m1 = xl.y + xr.y;
            float l0 = m0 > 0.f ? m0 : NEG_SLOPE * m0;
            float l1 = m1 > 0.f ? m1 : NEG_SLOPE * m1;
            float p = l0 * a0 + l1 * a1;
            p += __shfl_xor_sync(0xffffffffu, p, 1);
            p += __shfl_xor_sync(0xffffffffu, p, 2);   // per-head logit (4-lane group)
            float ev = __expf(p);
            acc0 += ev * xl.x; acc1 += ev * xl.y; s += ev;
        }
    }
    float inv = 1.f / s;
    *(float2*)(g_out1 + dst * 64 + lane * 2) = make_float2(acc0 * inv, acc1 * inv);
}

// ---------------- GEMM2: elu(out1+bias1) [N,64] @ [64,40|40] -> g_hl2, g_hr2 ----
__global__ void gemm2_kernel(const float* __restrict__ bias1,
                             const float* __restrict__ Wl2, const float* __restrict__ bl2,
                             const float* __restrict__ Wr2, const float* __restrict__ br2) {
    __shared__ float Ws[64][80];
    __shared__ float As[32][65];
    const int tid = threadIdx.x;
    const int node0 = blockIdx.x * 32;

    for (int i = tid; i < 64 * 80; i += 256) {
        int k = i / 80, c = i % 80;
        Ws[k][c] = (c < 40) ? Wl2[k * 40 + c] : Wr2[k * 40 + c - 40];
    }
    for (int i = tid; i < 32 * 64; i += 256) {
        int n = i >> 6, c = i & 63;
        int gn = node0 + n;
        float v = 0.f;
        if (gn < NN) v = g_out1[gn * 64 + c] + bias1[c];
        As[n][c] = v > 0.f ? v : (__expf(v) - 1.0f);   // ELU
    }
    __syncthreads();

    const int n = tid >> 3;
    const int cg = tid & 7;
    float acc[10];
#pragma unroll
    for (int j = 0; j < 10; j++) acc[j] = 0.f;
#pragma unroll 8
    for (int k = 0; k < 64; k++) {
        float a = As[n][k];
#pragma unroll
        for (int j = 0; j < 10; j++) acc[j] += a * Ws[k][cg * 10 + j];
    }
    int gn = node0 + n;
    if (gn < NN) {
#pragma unroll
        for (int j = 0; j < 10; j++) {
            int c = cg * 10 + j;
            float v = acc[j];
            if (c < 40) g_hl2[gn * 40 + c]      = v + bl2[c];
            else        g_hr2[gn * 40 + c - 40] = v + br2[c - 40];
        }
    }
}

// ---------------- layer2 fused: warp per dst, 20 active lanes x float2 ----------
__global__ void l2_fused(const float* __restrict__ att) {
    int w = (blockIdx.x * blockDim.x + threadIdx.x) >> 5;
    int lane = threadIdx.x & 31;
    if (w >= NN) return;
    const int dst = w;
    const int beg = g_offs[dst], end = g_offs[dst + 1];
    const bool act = lane < 20;

    float2 hr = act ? *(const float2*)(g_hr2 + dst * 40 + lane * 2)
                    : make_float2(0.f, 0.f);
    float a0 = act ? __ldg(att + lane * 2)     : 0.f;
    float a1 = act ? __ldg(att + lane * 2 + 1) : 0.f;

    float acc0 = 0.f, acc1 = 0.f, s = 0.f;

    for (int base = beg; base < end; base += 32) {
        int mysrc = (base + lane < end) ? g_csr_src[base + lane] : 0;
        int cnt = min(32, end - base);

        int src_n = __shfl_sync(0xffffffffu, mysrc, 0);
        float2 hl_n = act ? *(const float2*)(g_hl2 + src_n * 40 + lane * 2)
                          : make_float2(0.f, 0.f);
        for (int j = 0; j < cnt; j++) {
            float2 hl = hl_n;
            if (j + 1 < cnt) {
                int sj = __shfl_sync(0xffffffffu, mysrc, j + 1);
                if (act) hl_n = *(const float2*)(g_hl2 + sj * 40 + lane * 2);
            }
            float m0 = hl.x + hr.x, m1 = hl.y + hr.y;
            float l0 = m0 > 0.f ? m0 : NEG_SLOPE * m0;
            float l1 = m1 > 0.f ? m1 : NEG_SLOPE * m1;
            float p = l0 * a0 + l1 * a1;
#pragma unroll
            for (int off = 16; off > 0; off >>= 1)
                p += __shfl_xor_sync(0xffffffffu, p, off);
            float ev = __expf(p);
            acc0 += ev * hl.x; acc1 += ev * hl.y; s += ev;
        }
    }
    float inv = 1.f / s;
    if (act)
        *(float2*)(g_out2 + dst * 40 + lane * 2) = make_float2(acc0 * inv, acc1 * inv);
}

// ---------------- final: out2 + bias2, log_softmax over 40 ----------------------
__global__ void final_lsm(const float* __restrict__ bias2, float* __restrict__ out) {
    int gw = (blockIdx.x * blockDim.x + threadIdx.x) >> 5;
    int lane = threadIdx.x & 31;
    if (gw >= NN) return;
    const float* row = g_out2 + gw * 40;
    float v0 = row[lane] + bias2[lane];
    float v1 = (lane < 8) ? (row[32 + lane] + bias2[32 + lane]) : -FLT_MAX;
    float m = fmaxf(v0, v1);
#pragma unroll
    for (int off = 16; off > 0; off >>= 1) m = fmaxf(m, __shfl_xor_sync(0xffffffffu, m, off));
    float s = __expf(v0 - m) + ((lane < 8) ? __expf(v1 - m) : 0.f);
#pragma unroll
    for (int off = 16; off > 0; off >>= 1) s += __shfl_xor_sync(0xffffffffu, s, off);
    float lse = m + logf(s);
    out[gw * 40 + lane] = v0 - lse;
    if (lane < 8) out[gw * 40 + 32 + lane] = v1 - lse;
}

// ---------------- launch --------------------------------------------------------
extern "C" void kernel_launch(void* const* d_in, const int* in_sizes, int n_in,
                              void* d_out, int out_size) {
    const float* x    = (const float*)d_in[0];
    const int*   ei   = (const int*)  d_in[1];
    const float* Wl1  = (const float*)d_in[2];
    const float* bl1  = (const float*)d_in[3];
    const float* Wr1  = (const float*)d_in[4];
    const float* br1  = (const float*)d_in[5];
    const float* att1 = (const float*)d_in[6];
    const float* bias1= (const float*)d_in[7];
    const float* Wl2  = (const float*)d_in[8];
    const float* bl2  = (const float*)d_in[9];
    const float* Wr2  = (const float*)d_in[10];
    const float* br2  = (const float*)d_in[11];
    const float* att2 = (const float*)d_in[12];
    const float* bias2= (const float*)d_in[13];
    float* out = (float*)d_out;

    const int E = in_sizes[1] / 2;
    const int Etot = E + NN;
    const int nb = (NN + SCAN_B - 1) / SCAN_B;

    // CSR build (shared by both layers)
    csr_init<<<(NN + 255) / 256, 256>>>();
    csr_hist<<<(E + 255) / 256, 256>>>(ei, E);
    scan1<<<nb, SCAN_B>>>();
    scan2<<<1, 128>>>(nb);
    scan3<<<(NN + 255) / 256, 256>>>();
    csr_scatter<<<(Etot + 255) / 256, 256>>>(ei, E, Etot);

    gemm1_tc<<<NPAD / 128, 256>>>(x, Wl1, Wr1);
    l1_fused<<<(NN * 32 + 255) / 256, 256>>>(att1, bl1, br1);
    gemm2_kernel<<<(NN + 31) / 32, 256>>>(bias1, Wl2, bl2, Wr2, br2);
    l2_fused<<<(NN * 32 + 255) / 256, 256>>>(att2);
    final_lsm<<<(NN + 7) / 8, 256>>>(bias2, out);
}

// round 7
// speedup vs baseline: 2.8600x; 1.1745x over previous
#include <cuda_runtime.h>
#include <cuda_bf16.h>
#include <mma.h>
#include <math.h>
#include <float.h>

using namespace nvcuda;

#define NN 100000
#define NPAD 100096    // NN rounded up to 128
#define IN_DIM 256
#define L1_OUT 64
#define HEADS 8
#define HID 8
#define OUT_DIM 40
#define EMAX 1700000
#define NEG_SLOPE 0.2f
#define SCAN_B 1024

// ---------------- scratch ---------------------------------------------------------
__device__ float g_x1[NPAD * 128];    // [xl | xr] combined, stride 128
__device__ float g_out1[NPAD * 64];   // layer-1 output (padded rows read by gemm2)
__device__ float g_h2[NPAD * 80];     // [hl | hr] combined, stride 80

__device__ int g_cnt[NN];
__device__ int g_incl[NN];
__device__ int g_blksum[128];
__device__ int g_offs[NN + 1];
__device__ int g_cursor[NN];
__device__ int g_csr_src[EMAX];

// ---------------- CSR build -------------------------------------------------------
__global__ void csr_init() {
    int i = blockIdx.x * blockDim.x + threadIdx.x;
    if (i < NN) g_cnt[i] = 1;    // self loop
}

__global__ void csr_hist(const int* __restrict__ ei, int E) {
    int e = blockIdx.x * blockDim.x + threadIdx.x;
    if (e < E) atomicAdd(&g_cnt[ei[E + e]], 1);
}

__global__ void scan1() {
    __shared__ int sm[SCAN_B];
    int i = blockIdx.x * SCAN_B + threadIdx.x;
    int v = (i < NN) ? g_cnt[i] : 0;
    sm[threadIdx.x] = v;
    __syncthreads();
    for (int off = 1; off < SCAN_B; off <<= 1) {
        int t = (threadIdx.x >= off) ? sm[threadIdx.x - off] : 0;
        __syncthreads();
        sm[threadIdx.x] += t;
        __syncthreads();
    }
    if (i < NN) g_incl[i] = sm[threadIdx.x];
    if (threadIdx.x == SCAN_B - 1) g_blksum[blockIdx.x] = sm[threadIdx.x];
}

// scan3 with scan2 folded in: every block redundantly scans the 98 block sums.
__global__ void scan3(int nb) {
    __shared__ int bs[128];
    int tid = threadIdx.x;
    if (tid < 128) bs[tid] = (tid < nb) ? g_blksum[tid] : 0;
    __syncthreads();
    for (int off = 1; off < 128; off <<= 1) {
        int t = 0;
        if (tid < 128 && tid >= off) t = bs[tid - off];
        __syncthreads();
        if (tid < 128) bs[tid] += t;
        __syncthreads();
    }
    int i = blockIdx.x * 128 + tid;
    if (tid >= 128 || i >= NN) return;
    int blk = i / SCAN_B;
    int add = (blk > 0) ? bs[blk - 1] : 0;
    int tot = g_incl[i] + add;
    g_offs[i + 1] = tot;
    g_cursor[i] = tot - g_cnt[i];
    if (i == 0) g_offs[0] = 0;
}

__global__ void csr_scatter(const int* __restrict__ ei, int E, int Etot) {
    int e = blockIdx.x * blockDim.x + threadIdx.x;
    if (e >= Etot) return;
    int src, dst;
    if (e < E) { src = ei[e]; dst = ei[E + e]; } else { src = dst = e - E; }
    int pos = atomicAdd(&g_cursor[dst], 1);
    g_csr_src[pos] = src;
}

// ---------------- GEMM1 (tf32 wmma): X[N,256] @ [Wl|Wr] -> g_x1[N,128] -----------
#define ASTRIDE 40
#define BSTRIDE 136

__global__ void gemm1_tc(const float* __restrict__ x,
                         const float* __restrict__ Wl,
                         const float* __restrict__ Wr) {
    __shared__ float As[128][ASTRIDE];
    __shared__ float Bs[32][BSTRIDE];
    const int tid = threadIdx.x;
    const int w = tid >> 5;
    const int warp_m = w & 3;
    const int warp_n = w >> 2;
    const int block_row = blockIdx.x * 128;

    wmma::fragment<wmma::accumulator, 16, 16, 8, float> acc[2][4];
#pragma unroll
    for (int mt = 0; mt < 2; mt++)
#pragma unroll
        for (int nt = 0; nt < 4; nt++) wmma::fill_fragment(acc[mt][nt], 0.f);

    for (int k0 = 0; k0 < IN_DIM; k0 += 32) {
#pragma unroll
        for (int i = 0; i < 4; i++) {
            int f = tid + i * 256;
            int r = f >> 3, c = (f & 7) * 4;
            int gr = block_row + r;
            float4 v = make_float4(0.f, 0.f, 0.f, 0.f);
            if (gr < NN) v = *(const float4*)(x + (size_t)gr * IN_DIM + k0 + c);
            As[r][c + 0] = wmma::__float_to_tf32(v.x);
            As[r][c + 1] = wmma::__float_to_tf32(v.y);
            As[r][c + 2] = wmma::__float_to_tf32(v.z);
            As[r][c + 3] = wmma::__float_to_tf32(v.w);
        }
#pragma unroll
        for (int i = 0; i < 4; i++) {
            int f = tid + i * 256;
            int r = f >> 5, c = (f & 31) * 4;
            const float* src = (c < 64) ? (Wl + (size_t)(k0 + r) * 64 + c)
                                        : (Wr + (size_t)(k0 + r) * 64 + c - 64);
            float4 v = *(const float4*)src;
            Bs[r][c + 0] = wmma::__float_to_tf32(v.x);
            Bs[r][c + 1] = wmma::__float_to_tf32(v.y);
            Bs[r][c + 2] = wmma::__float_to_tf32(v.z);
            Bs[r][c + 3] = wmma::__float_to_tf32(v.w);
        }
        __syncthreads();

#pragma unroll
        for (int kk = 0; kk < 32; kk += 8) {
            wmma::fragment<wmma::matrix_a, 16, 16, 8, wmma::precision::tf32, wmma::row_major> af[2];
            wmma::fragment<wmma::matrix_b, 16, 16, 8, wmma::precision::tf32, wmma::row_major> bf[4];
#pragma unroll
            for (int mt = 0; mt < 2; mt++)
                wmma::load_matrix_sync(af[mt], &As[warp_m * 32 + mt * 16][kk], ASTRIDE);
#pragma unroll
            for (int nt = 0; nt < 4; nt++)
                wmma::load_matrix_sync(bf[nt], &Bs[kk][warp_n * 64 + nt * 16], BSTRIDE);
#pragma unroll
            for (int mt = 0; mt < 2; mt++)
#pragma unroll
                for (int nt = 0; nt < 4; nt++)
                    wmma::mma_sync(acc[mt][nt], af[mt], bf[nt], acc[mt][nt]);
        }
        __syncthreads();
    }

#pragma unroll
    for (int mt = 0; mt < 2; mt++) {
        int r0 = block_row + warp_m * 32 + mt * 16;
#pragma unroll
        for (int nt = 0; nt < 4; nt++) {
            int c0 = warp_n * 64 + nt * 16;
            wmma::store_matrix_sync(g_x1 + (size_t)r0 * 128 + c0, acc[mt][nt],
                                    128, wmma::mem_row_major);
        }
    }
}

// ---------------- layer1 fused: warp per dst, depth-3 gather pipeline ------------
__global__ void l1_fused(const float* __restrict__ att,
                         const float* __restrict__ bl, const float* __restrict__ br) {
    int w = (blockIdx.x * blockDim.x + threadIdx.x) >> 5;
    int lane = threadIdx.x & 31;
    if (w >= NN) return;
    const int dst = w;
    const int beg = g_offs[dst], end = g_offs[dst + 1];

    float bl0 = __ldg(bl + lane * 2), bl1 = __ldg(bl + lane * 2 + 1);
    float2 xr = *(const float2*)(g_x1 + (size_t)dst * 128 + 64 + lane * 2);
    xr.x += __ldg(br + lane * 2); xr.y += __ldg(br + lane * 2 + 1);
    float a0 = __ldg(att + lane * 2);
    float a1 = __ldg(att + lane * 2 + 1);

    float acc0 = 0.f, acc1 = 0.f, s = 0.f;

    for (int base = beg; base < end; base += 32) {
        int mysrc = (base + lane < end) ? g_csr_src[base + lane] : 0;
        int cnt = min(32, end - base);

        int s0 = __shfl_sync(0xffffffffu, mysrc, 0);
        float2 q0 = *(const float2*)(g_x1 + (size_t)s0 * 128 + lane * 2);
        float2 q1 = q0;
        if (cnt > 1) {
            int s1 = __shfl_sync(0xffffffffu, mysrc, 1);
            q1 = *(const float2*)(g_x1 + (size_t)s1 * 128 + lane * 2);
        }
        for (int j = 0; j < cnt; j++) {
            float2 xl = q0;
            q0 = q1;
            if (j + 2 < cnt) {
                int sn = __shfl_sync(0xffffffffu, mysrc, j + 2);
                q1 = *(const float2*)(g_x1 + (size_t)sn * 128 + lane * 2);
            }
            xl.x += bl0; xl.y += bl1;
            float m0 = xl.x + xr.x, m1 = xl.y + xr.y;
            float l0 = m0 > 0.f ? m0 : NEG_SLOPE * m0;
            float l1 = m1 > 0.f ? m1 : NEG_SLOPE * m1;
            float p = l0 * a0 + l1 * a1;
            p += __shfl_xor_sync(0xffffffffu, p, 1);
            p += __shfl_xor_sync(0xffffffffu, p, 2);   // per-head logit
            float ev = __expf(p);
            acc0 += ev * xl.x; acc1 += ev * xl.y; s += ev;
        }
    }
    float inv = 1.f / s;
    *(float2*)(g_out1 + (size_t)dst * 64 + lane * 2) = make_float2(acc0 * inv, acc1 * inv);
}

// ---------------- GEMM2 (tf32 wmma): elu(out1+bias1)[N,64] @ [Wl2|Wr2] -> g_h2 ---
// 64 nodes per block, K=64 staged once, 4 warps (16 rows x 80 cols each).
#define A2STRIDE 68
#define B2STRIDE 88

__global__ void gemm2_tc(const float* __restrict__ bias1,
                         const float* __restrict__ Wl2,
                         const float* __restrict__ Wr2) {
    __shared__ float As[64][A2STRIDE];
    __shared__ float Bs[64][B2STRIDE];
    const int tid = threadIdx.x;   // 128 threads
    const int w = tid >> 5;
    const int node0 = blockIdx.x * 64;

    // Stage A: elu(out1 + bias1), tf32.  64x64 = 1024 float4, 8 per thread.
#pragma unroll
    for (int i = 0; i < 8; i++) {
        int f = tid + i * 128;
        int r = f >> 4, c = (f & 15) * 4;
        float4 v = *(const float4*)(g_out1 + (size_t)(node0 + r) * 64 + c);
        float4 b = *(const float4*)(bias1 + c);
        v.x += b.x; v.y += b.y; v.z += b.z; v.w += b.w;
        v.x = v.x > 0.f ? v.x : (__expf(v.x) - 1.f);
        v.y = v.y > 0.f ? v.y : (__expf(v.y) - 1.f);
        v.z = v.z > 0.f ? v.z : (__expf(v.z) - 1.f);
        v.w = v.w > 0.f ? v.w : (__expf(v.w) - 1.f);
        As[r][c + 0] = wmma::__float_to_tf32(v.x);
        As[r][c + 1] = wmma::__float_to_tf32(v.y);
        As[r][c + 2] = wmma::__float_to_tf32(v.z);
        As[r][c + 3] = wmma::__float_to_tf32(v.w);
    }
    // Stage B: [Wl2 | Wr2] 64x80 = 1280 float4, 10 per thread.
#pragma unroll
    for (int i = 0; i < 10; i++) {
        int f = tid + i * 128;
        int r = f / 20, c = (f % 20) * 4;
        const float* src = (c < 40) ? (Wl2 + (size_t)r * 40 + c)
                                    : (Wr2 + (size_t)r * 40 + c - 40);
        float4 v = *(const float4*)src;
        Bs[r][c + 0] = wmma::__float_to_tf32(v.x);
        Bs[r][c + 1] = wmma::__float_to_tf32(v.y);
        Bs[r][c + 2] = wmma::__float_to_tf32(v.z);
        Bs[r][c + 3] = wmma::__float_to_tf32(v.w);
    }
    __syncthreads();

    wmma::fragment<wmma::accumulator, 16, 16, 8, float> acc[5];
#pragma unroll
    for (int nt = 0; nt < 5; nt++) wmma::fill_fragment(acc[nt], 0.f);

#pragma unroll
    for (int kk = 0; kk < 64; kk += 8) {
        wmma::fragment<wmma::matrix_a, 16, 16, 8, wmma::precision::tf32, wmma::row_major> af;
        wmma::load_matrix_sync(af, &As[w * 16][kk], A2STRIDE);
#pragma unroll
        for (int nt = 0; nt < 5; nt++) {
            wmma::fragment<wmma::matrix_b, 16, 16, 8, wmma::precision::tf32, wmma::row_major> bf;
            wmma::load_matrix_sync(bf, &Bs[kk][nt * 16], B2STRIDE);
            wmma::mma_sync(acc[nt], af, bf, acc[nt]);
        }
    }

    int r0 = node0 + w * 16;
#pragma unroll
    for (int nt = 0; nt < 5; nt++)
        wmma::store_matrix_sync(g_h2 + (size_t)r0 * 80 + nt * 16, acc[nt],
                                80, wmma::mem_row_major);
}

// ---------------- layer2 fused + final log_softmax: warp per dst ----------------
__global__ void l2_final(const float* __restrict__ att,
                         const float* __restrict__ bl2, const float* __restrict__ br2,
                         const float* __restrict__ bias2, float* __restrict__ out) {
    int w = (blockIdx.x * blockDim.x + threadIdx.x) >> 5;
    int lane = threadIdx.x & 31;
    if (w >= NN) return;
    const int dst = w;
    const int beg = g_offs[dst], end = g_offs[dst + 1];
    const bool act = lane < 20;

    float bl0 = act ? __ldg(bl2 + lane * 2)     : 0.f;
    float bl1 = act ? __ldg(bl2 + lane * 2 + 1) : 0.f;
    float2 hr = act ? *(const float2*)(g_h2 + (size_t)dst * 80 + 40 + lane * 2)
                    : make_float2(0.f, 0.f);
    if (act) { hr.x += __ldg(br2 + lane * 2); hr.y += __ldg(br2 + lane * 2 + 1); }
    float a0 = act ? __ldg(att + lane * 2)     : 0.f;
    float a1 = act ? __ldg(att + lane * 2 + 1) : 0.f;

    float acc0 = 0.f, acc1 = 0.f, s = 0.f;

    for (int base = beg; base < end; base += 32) {
        int mysrc = (base + lane < end) ? g_csr_src[base + lane] : 0;
        int cnt = min(32, end - base);

        int s0 = __shfl_sync(0xffffffffu, mysrc, 0);
        float2 q0 = act ? *(const float2*)(g_h2 + (size_t)s0 * 80 + lane * 2)
                        : make_float2(0.f, 0.f);
        float2 q1 = q0;
        if (cnt > 1) {
            int s1 = __shfl_sync(0xffffffffu, mysrc, 1);
            if (act) q1 = *(const float2*)(g_h2 + (size_t)s1 * 80 + lane * 2);
        }
        for (int j = 0; j < cnt; j++) {
            float2 hl = q0;
            q0 = q1;
            if (j + 2 < cnt) {
                int sn = __shfl_sync(0xffffffffu, mysrc, j + 2);
                if (act) q1 = *(const float2*)(g_h2 + (size_t)sn * 80 + lane * 2);
            }
            hl.x += bl0; hl.y += bl1;
            float m0 = hl.x + hr.x, m1 = hl.y + hr.y;
            float l0 = m0 > 0.f ? m0 : NEG_SLOPE * m0;
            float l1 = m1 > 0.f ? m1 : NEG_SLOPE * m1;
            float p = l0 * a0 + l1 * a1;
#pragma unroll
            for (int off = 16; off > 0; off >>= 1)
                p += __shfl_xor_sync(0xffffffffu, p, off);
            float ev = __expf(p);
            acc0 += ev * hl.x; acc1 += ev * hl.y; s += ev;
        }
    }
    float inv = 1.f / s;
    float v0 = acc0 * inv, v1 = acc1 * inv;
    if (act) {
        v0 += __ldg(bias2 + lane * 2);
        v1 += __ldg(bias2 + lane * 2 + 1);
    }
    // warp logsumexp over the 40 values held by 20 lanes
    float m = act ? fmaxf(v0, v1) : -FLT_MAX;
#pragma unroll
    for (int off = 16; off > 0; off >>= 1)
        m = fmaxf(m, __shfl_xor_sync(0xffffffffu, m, off));
    float se = act ? (__expf(v0 - m) + __expf(v1 - m)) : 0.f;
#pragma unroll
    for (int off = 16; off > 0; off >>= 1)
        se += __shfl_xor_sync(0xffffffffu, se, off);
    float lse = m + logf(se);
    if (act)
        *(float2*)(out + (size_t)dst * 40 + lane * 2) = make_float2(v0 - lse, v1 - lse);
}

// ---------------- launch ----------------------------------------------------------
extern "C" void kernel_launch(void* const* d_in, const int* in_sizes, int n_in,
                              void* d_out, int out_size) {
    const float* x    = (const float*)d_in[0];
    const int*   ei   = (const int*)  d_in[1];
    const float* Wl1  = (const float*)d_in[2];
    const float* bl1  = (const float*)d_in[3];
    const float* Wr1  = (const float*)d_in[4];
    const float* br1  = (const float*)d_in[5];
    const float* att1 = (const float*)d_in[6];
    const float* bias1= (const float*)d_in[7];
    const float* Wl2  = (const float*)d_in[8];
    const float* bl2  = (const float*)d_in[9];
    const float* Wr2  = (const float*)d_in[10];
    const float* br2  = (const float*)d_in[11];
    const float* att2 = (const float*)d_in[12];
    const float* bias2= (const float*)d_in[13];
    float* out = (float*)d_out;

    const int E = in_sizes[1] / 2;
    const int Etot = E + NN;
    const int nb = (NN + SCAN_B - 1) / SCAN_B;

    csr_init<<<(NN + 255) / 256, 256>>>();                 // 0
    csr_hist<<<(E + 255) / 256, 256>>>(ei, E);             // 1
    scan1<<<nb, SCAN_B>>>();                               // 2
    gemm1_tc<<<NPAD / 128, 256>>>(x, Wl1, Wr1);            // 3  <- profiled slot
    scan3<<<(NN + 127) / 128, 128>>>(nb);                  // 4
    csr_scatter<<<(Etot + 255) / 256, 256>>>(ei, E, Etot); // 5
    l1_fused<<<(NN * 32 + 255) / 256, 256>>>(att1, bl1, br1);          // 6
    gemm2_tc<<<NPAD / 64, 128>>>(bias1, Wl2, Wr2);         // 7
    l2_final<<<(NN * 32 + 255) / 256, 256>>>(att2, bl2, br2, bias2, out); // 8
}

// round 8
// speedup vs baseline: 2.9870x; 1.0444x over previous
#include <cuda_runtime.h>
#include <cuda_bf16.h>
#include <cuda_pipeline.h>
#include <mma.h>
#include <math.h>
#include <float.h>

using namespace nvcuda;

#define NN 100000
#define NPAD 100096    // NN rounded up to 128
#define IN_DIM 256
#define L1_OUT 64
#define HEADS 8
#define HID 8
#define OUT_DIM 40
#define EMAX 1700000
#define NEG_SLOPE 0.2f
#define SCAN_B 1024

// ---------------- scratch ---------------------------------------------------------
__device__ float g_x1[NPAD * 128];    // [xl | xr] combined, stride 128
__device__ float g_out1[NPAD * 64];
__device__ float g_h2[NPAD * 80];     // [hl | hr] combined, stride 80

__device__ int g_cnt[NN];
__device__ int g_incl[NN];
__device__ int g_blksum[128];
__device__ int g_offs[NN + 1];
__device__ int g_cursor[NN];
__device__ int g_csr_src[EMAX];

// ---------------- CSR build -------------------------------------------------------
__global__ void csr_init() {
    int i = blockIdx.x * blockDim.x + threadIdx.x;
    if (i < NN) g_cnt[i] = 1;    // self loop
}

__global__ void csr_hist(const int* __restrict__ ei, int E) {
    int e = blockIdx.x * blockDim.x + threadIdx.x;
    if (e < E) atomicAdd(&g_cnt[ei[E + e]], 1);
}

__global__ void scan1() {
    __shared__ int sm[SCAN_B];
    int i = blockIdx.x * SCAN_B + threadIdx.x;
    int v = (i < NN) ? g_cnt[i] : 0;
    sm[threadIdx.x] = v;
    __syncthreads();
    for (int off = 1; off < SCAN_B; off <<= 1) {
        int t = (threadIdx.x >= off) ? sm[threadIdx.x - off] : 0;
        __syncthreads();
        sm[threadIdx.x] += t;
        __syncthreads();
    }
    if (i < NN) g_incl[i] = sm[threadIdx.x];
    if (threadIdx.x == SCAN_B - 1) g_blksum[blockIdx.x] = sm[threadIdx.x];
}

// scan3 with scan2 folded in: every block redundantly scans the block sums.
__global__ void scan3(int nb) {
    __shared__ int bs[128];
    int tid = threadIdx.x;
    if (tid < 128) bs[tid] = (tid < nb) ? g_blksum[tid] : 0;
    __syncthreads();
    for (int off = 1; off < 128; off <<= 1) {
        int t = 0;
        if (tid < 128 && tid >= off) t = bs[tid - off];
        __syncthreads();
        if (tid < 128) bs[tid] += t;
        __syncthreads();
    }
    int i = blockIdx.x * 128 + tid;
    if (tid >= 128 || i >= NN) return;
    int blk = i / SCAN_B;
    int add = (blk > 0) ? bs[blk - 1] : 0;
    int tot = g_incl[i] + add;
    g_offs[i + 1] = tot;
    g_cursor[i] = tot - g_cnt[i];
    if (i == 0) g_offs[0] = 0;
}

__global__ void csr_scatter(const int* __restrict__ ei, int E, int Etot) {
    int e = blockIdx.x * blockDim.x + threadIdx.x;
    if (e >= Etot) return;
    int src, dst;
    if (e < E) { src = ei[e]; dst = ei[E + e]; } else { src = dst = e - E; }
    int pos = atomicAdd(&g_cursor[dst], 1);
    g_csr_src[pos] = src;
}

// ---------------- GEMM1 (tf32 wmma + cp.async double buffer) ---------------------
// X[N,256] @ [Wl|Wr] -> g_x1[N,128].  Block 128x128x32, 2-stage cp.async.
// fp32 bits fed raw to HMMA.TF32 (hardware truncates mantissa).
#define ASTRIDE 40
#define BSTRIDE 136
#define A_ST (128 * ASTRIDE)
#define B_ST (32 * BSTRIDE)
#define G1_SMEM ((2 * A_ST + 2 * B_ST) * 4)

__global__ void __launch_bounds__(256, 2)
gemm1_tc(const float* __restrict__ x,
         const float* __restrict__ Wl,
         const float* __restrict__ Wr) {
    extern __shared__ float smem[];
    float* Asm = smem;               // 2 stages of [128][ASTRIDE]
    float* Bsm = smem + 2 * A_ST;    // 2 stages of [32][BSTRIDE]

    const int tid = threadIdx.x;
    const int w = tid >> 5;
    const int warp_m = w & 3;
    const int warp_n = w >> 2;
    const int block_row = blockIdx.x * 128;

    // per-thread fixed copy slots
    const int ar = tid >> 1;                 // A: row 0..127 (2 threads/row)
    const int ac = (tid & 1) * 16;           // A: col 0 or 16 (16 floats each)
    const int br_ = tid >> 3;                // B: row 0..31 (8 threads/row)
    const int bc = (tid & 7) * 16;           // B: col 0..112 step 16

    auto load_stage = [&](int s, int k0) {
        // A: each thread copies 16 floats = 4x16B
        int gr = min(block_row + ar, NN - 1);
        const float* asrc = x + (size_t)gr * IN_DIM + k0 + ac;
        float* adst = Asm + s * A_ST + ar * ASTRIDE + ac;
#pragma unroll
        for (int i = 0; i < 4; i++)
            __pipeline_memcpy_async(adst + i * 4, asrc + i * 4, 16);
        // B: each thread copies 16 floats = 4x16B
        const float* bsrc = (bc < 64) ? (Wl + (size_t)(k0 + br_) * 64 + bc)
                                      : (Wr + (size_t)(k0 + br_) * 64 + bc - 64);
        float* bdst = Bsm + s * B_ST + br_ * BSTRIDE + bc;
#pragma unroll
        for (int i = 0; i < 4; i++)
            __pipeline_memcpy_async(bdst + i * 4, bsrc + i * 4, 16);
    };

    wmma::fragment<wmma::accumulator, 16, 16, 8, float> acc[2][4];
#pragma unroll
    for (int mt = 0; mt < 2; mt++)
#pragma unroll
        for (int nt = 0; nt < 4; nt++) wmma::fill_fragment(acc[mt][nt], 0.f);

    load_stage(0, 0);
    __pipeline_commit();

    int s = 0;
    for (int k0 = 0; k0 < IN_DIM; k0 += 32) {
        if (k0 + 32 < IN_DIM) load_stage(s ^ 1, k0 + 32);
        __pipeline_commit();
        __pipeline_wait_prior(1);   // stage s fully arrived
        __syncthreads();

        const float* Acur = Asm + s * A_ST;
        const float* Bcur = Bsm + s * B_ST;
#pragma unroll
        for (int kk = 0; kk < 32; kk += 8) {
            wmma::fragment<wmma::matrix_a, 16, 16, 8, wmma::precision::tf32, wmma::row_major> af[2];
            wmma::fragment<wmma::matrix_b, 16, 16, 8, wmma::precision::tf32, wmma::row_major> bf[4];
#pragma unroll
            for (int mt = 0; mt < 2; mt++)
                wmma::load_matrix_sync(af[mt],
                    Acur + (warp_m * 32 + mt * 16) * ASTRIDE + kk, ASTRIDE);
#pragma unroll
            for (int nt = 0; nt < 4; nt++)
                wmma::load_matrix_sync(bf[nt],
                    Bcur + kk * BSTRIDE + warp_n * 64 + nt * 16, BSTRIDE);
#pragma unroll
            for (int mt = 0; mt < 2; mt++)
#pragma unroll
                for (int nt = 0; nt < 4; nt++)
                    wmma::mma_sync(acc[mt][nt], af[mt], bf[nt], acc[mt][nt]);
        }
        __syncthreads();   // stage s reusable for the next prefetch
        s ^= 1;
    }

#pragma unroll
    for (int mt = 0; mt < 2; mt++) {
        int r0 = block_row + warp_m * 32 + mt * 16;
#pragma unroll
        for (int nt = 0; nt < 4; nt++) {
            int c0 = warp_n * 64 + nt * 16;
            wmma::store_matrix_sync(g_x1 + (size_t)r0 * 128 + c0, acc[mt][nt],
                                    128, wmma::mem_row_major);
        }
    }
}

// ---------------- layer1 fused: warp per dst, depth-3 gather pipeline ------------
__global__ void l1_fused(const float* __restrict__ att,
                         const float* __restrict__ bl, const float* __restrict__ br) {
    int w = (blockIdx.x * blockDim.x + threadIdx.x) >> 5;
    int lane = threadIdx.x & 31;
    if (w >= NN) return;
    const int dst = w;
    const int beg = g_offs[dst], end = g_offs[dst + 1];

    float bl0 = __ldg(bl + lane * 2), bl1 = __ldg(bl + lane * 2 + 1);
    float2 xr = *(const float2*)(g_x1 + (size_t)dst * 128 + 64 + lane * 2);
    xr.x += __ldg(br + lane * 2); xr.y += __ldg(br + lane * 2 + 1);
    float a0 = __ldg(att + lane * 2);
    float a1 = __ldg(att + lane * 2 + 1);

    float acc0 = 0.f, acc1 = 0.f, s = 0.f;

    for (int base = beg; base < end; base += 32) {
        int mysrc = (base + lane < end) ? g_csr_src[base + lane] : 0;
        int cnt = min(32, end - base);

        int s0 = __shfl_sync(0xffffffffu, mysrc, 0);
        float2 q0 = *(const float2*)(g_x1 + (size_t)s0 * 128 + lane * 2);
        float2 q1 = q0;
        if (cnt > 1) {
            int s1 = __shfl_sync(0xffffffffu, mysrc, 1);
            q1 = *(const float2*)(g_x1 + (size_t)s1 * 128 + lane * 2);
        }
        for (int j = 0; j < cnt; j++) {
            float2 xl = q0;
            q0 = q1;
            if (j + 2 < cnt) {
                int sn = __shfl_sync(0xffffffffu, mysrc, j + 2);
                q1 = *(const float2*)(g_x1 + (size_t)sn * 128 + lane * 2);
            }
            xl.x += bl0; xl.y += bl1;
            float m0 = xl.x + xr.x, m1 = xl.y + xr.y;
            float l0 = m0 > 0.f ? m0 : NEG_SLOPE * m0;
            float l1 = m1 > 0.f ? m1 : NEG_SLOPE * m1;
            float p = l0 * a0 + l1 * a1;
            p += __shfl_xor_sync(0xffffffffu, p, 1);
            p += __shfl_xor_sync(0xffffffffu, p, 2);   // per-head logit
            float ev = __expf(p);
            acc0 += ev * xl.x; acc1 += ev * xl.y; s += ev;
        }
    }
    float inv = 1.f / s;
    *(float2*)(g_out1 + (size_t)dst * 64 + lane * 2) = make_float2(acc0 * inv, acc1 * inv);
}

// ---------------- GEMM2 (tf32 wmma): elu(out1+bias1)[N,64] @ [Wl2|Wr2] -> g_h2 ---
#define A2STRIDE 68
#define B2STRIDE 88

__global__ void gemm2_tc(const float* __restrict__ bias1,
                         const float* __restrict__ Wl2,
                         const float* __restrict__ Wr2) {
    __shared__ float As[64][A2STRIDE];
    __shared__ float Bs[64][B2STRIDE];
    const int tid = threadIdx.x;   // 128 threads
    const int w = tid >> 5;
    const int node0 = blockIdx.x * 64;

#pragma unroll
    for (int i = 0; i < 8; i++) {
        int f = tid + i * 128;
        int r = f >> 4, c = (f & 15) * 4;
        float4 v = *(const float4*)(g_out1 + (size_t)(node0 + r) * 64 + c);
        float4 b = *(const float4*)(bias1 + c);
        v.x += b.x; v.y += b.y; v.z += b.z; v.w += b.w;
        v.x = v.x > 0.f ? v.x : (__expf(v.x) - 1.f);
        v.y = v.y > 0.f ? v.y : (__expf(v.y) - 1.f);
        v.z = v.z > 0.f ? v.z : (__expf(v.z) - 1.f);
        v.w = v.w > 0.f ? v.w : (__expf(v.w) - 1.f);
        As[r][c + 0] = wmma::__float_to_tf32(v.x);
        As[r][c + 1] = wmma::__float_to_tf32(v.y);
        As[r][c + 2] = wmma::__float_to_tf32(v.z);
        As[r][c + 3] = wmma::__float_to_tf32(v.w);
    }
#pragma unroll
    for (int i = 0; i < 10; i++) {
        int f = tid + i * 128;
        int r = f / 20, c = (f % 20) * 4;
        const float* src = (c < 40) ? (Wl2 + (size_t)r * 40 + c)
                                    : (Wr2 + (size_t)r * 40 + c - 40);
        float4 v = *(const float4*)src;
        Bs[r][c + 0] = wmma::__float_to_tf32(v.x);
        Bs[r][c + 1] = wmma::__float_to_tf32(v.y);
        Bs[r][c + 2] = wmma::__float_to_tf32(v.z);
        Bs[r][c + 3] = wmma::__float_to_tf32(v.w);
    }
    __syncthreads();

    wmma::fragment<wmma::accumulator, 16, 16, 8, float> acc[5];
#pragma unroll
    for (int nt = 0; nt < 5; nt++) wmma::fill_fragment(acc[nt], 0.f);

#pragma unroll
    for (int kk = 0; kk < 64; kk += 8) {
        wmma::fragment<wmma::matrix_a, 16, 16, 8, wmma::precision::tf32, wmma::row_major> af;
        wmma::load_matrix_sync(af, &As[w * 16][kk], A2STRIDE);
#pragma unroll
        for (int nt = 0; nt < 5; nt++) {
            wmma::fragment<wmma::matrix_b, 16, 16, 8, wmma::precision::tf32, wmma::row_major> bf;
            wmma::load_matrix_sync(bf, &Bs[kk][nt * 16], B2STRIDE);
            wmma::mma_sync(acc[nt], af, bf, acc[nt]);
        }
    }

    int r0 = node0 + w * 16;
#pragma unroll
    for (int nt = 0; nt < 5; nt++)
        wmma::store_matrix_sync(g_h2 + (size_t)r0 * 80 + nt * 16, acc[nt],
                                80, wmma::mem_row_major);
}

// ---------------- layer2 fused + final log_softmax: warp per dst ----------------
__global__ void l2_final(const float* __restrict__ att,
                         const float* __restrict__ bl2, const float* __restrict__ br2,
                         const float* __restrict__ bias2, float* __restrict__ out) {
    int w = (blockIdx.x * blockDim.x + threadIdx.x) >> 5;
    int lane = threadIdx.x & 31;
    if (w >= NN) return;
    const int dst = w;
    const int beg = g_offs[dst], end = g_offs[dst + 1];
    const bool act = lane < 20;

    float bl0 = act ? __ldg(bl2 + lane * 2)     : 0.f;
    float bl1 = act ? __ldg(bl2 + lane * 2 + 1) : 0.f;
    float2 hr = act ? *(const float2*)(g_h2 + (size_t)dst * 80 + 40 + lane * 2)
                    : make_float2(0.f, 0.f);
    if (act) { hr.x += __ldg(br2 + lane * 2); hr.y += __ldg(br2 + lane * 2 + 1); }
    float a0 = act ? __ldg(att + lane * 2)     : 0.f;
    float a1 = act ? __ldg(att + lane * 2 + 1) : 0.f;

    float acc0 = 0.f, acc1 = 0.f, s = 0.f;

    for (int base = beg; base < end; base += 32) {
        int mysrc = (base + lane < end) ? g_csr_src[base + lane] : 0;
        int cnt = min(32, end - base);

        int s0 = __shfl_sync(0xffffffffu, mysrc, 0);
        float2 q0 = act ? *(const float2*)(g_h2 + (size_t)s0 * 80 + lane * 2)
                        : make_float2(0.f, 0.f);
        float2 q1 = q0;
        if (cnt > 1) {
            int s1 = __shfl_sync(0xffffffffu, mysrc, 1);
            if (act) q1 = *(const float2*)(g_h2 + (size_t)s1 * 80 + lane * 2);
        }
        for (int j = 0; j < cnt; j++) {
            float2 hl = q0;
            q0 = q1;
            if (j + 2 < cnt) {
                int sn = __shfl_sync(0xffffffffu, mysrc, j + 2);
                if (act) q1 = *(const float2*)(g_h2 + (size_t)sn * 80 + lane * 2);
            }
            hl.x += bl0; hl.y += bl1;
            float m0 = hl.x + hr.x, m1 = hl.y + hr.y;
            float l0 = m0 > 0.f ? m0 : NEG_SLOPE * m0;
            float l1 = m1 > 0.f ? m1 : NEG_SLOPE * m1;
            float p = l0 * a0 + l1 * a1;
#pragma unroll
            for (int off = 16; off > 0; off >>= 1)
                p += __shfl_xor_sync(0xffffffffu, p, off);
            float ev = __expf(p);
            acc0 += ev * hl.x; acc1 += ev * hl.y; s += ev;
        }
    }
    float inv = 1.f / s;
    float v0 = acc0 * inv, v1 = acc1 * inv;
    if (act) {
        v0 += __ldg(bias2 + lane * 2);
        v1 += __ldg(bias2 + lane * 2 + 1);
    }
    float m = act ? fmaxf(v0, v1) : -FLT_MAX;
#pragma unroll
    for (int off = 16; off > 0; off >>= 1)
        m = fmaxf(m, __shfl_xor_sync(0xffffffffu, m, off));
    float se = act ? (__expf(v0 - m) + __expf(v1 - m)) : 0.f;
#pragma unroll
    for (int off = 16; off > 0; off >>= 1)
        se += __shfl_xor_sync(0xffffffffu, se, off);
    float lse = m + logf(se);
    if (act)
        *(float2*)(out + (size_t)dst * 40 + lane * 2) = make_float2(v0 - lse, v1 - lse);
}

// ---------------- launch ----------------------------------------------------------
extern "C" void kernel_launch(void* const* d_in, const int* in_sizes, int n_in,
                              void* d_out, int out_size) {
    const float* x    = (const float*)d_in[0];
    const int*   ei   = (const int*)  d_in[1];
    const float* Wl1  = (const float*)d_in[2];
    const float* bl1  = (const float*)d_in[3];
    const float* Wr1  = (const float*)d_in[4];
    const float* br1  = (const float*)d_in[5];
    const float* att1 = (const float*)d_in[6];
    const float* bias1= (const float*)d_in[7];
    const float* Wl2  = (const float*)d_in[8];
    const float* bl2  = (const float*)d_in[9];
    const float* Wr2  = (const float*)d_in[10];
    const float* br2  = (const float*)d_in[11];
    const float* att2 = (const float*)d_in[12];
    const float* bias2= (const float*)d_in[13];
    float* out = (float*)d_out;

    const int E = in_sizes[1] / 2;
    const int Etot = E + NN;
    const int nb = (NN + SCAN_B - 1) / SCAN_B;

    cudaFuncSetAttribute(gemm1_tc, cudaFuncAttributeMaxDynamicSharedMemorySize, G1_SMEM);

    csr_init<<<(NN + 255) / 256, 256>>>();                 // 0
    csr_hist<<<(E + 255) / 256, 256>>>(ei, E);             // 1
    scan1<<<nb, SCAN_B>>>();                               // 2
    gemm1_tc<<<NPAD / 128, 256, G1_SMEM>>>(x, Wl1, Wr1);   // 3  <- profiled slot
    scan3<<<(NN + 127) / 128, 128>>>(nb);                  // 4
    csr_scatter<<<(Etot + 255) / 256, 256>>>(ei, E, Etot); // 5
    l1_fused<<<(NN * 32 + 255) / 256, 256>>>(att1, bl1, br1);             // 6
    gemm2_tc<<<NPAD / 64, 128>>>(bias1, Wl2, Wr2);         // 7
    l2_final<<<(NN * 32 + 255) / 256, 256>>>(att2, bl2, br2, bias2, out); // 8
}

// round 9
// speedup vs baseline: 3.0064x; 1.0065x over previous
#include <cuda_runtime.h>
#include <cuda_bf16.h>
#include <cuda_pipeline.h>
#include <mma.h>
#include <math.h>
#include <float.h>

using namespace nvcuda;

#define NN 100000
#define NPAD 100096    // multiple of 128 (and 64)
#define IN_DIM 256
#define L1_OUT 64
#define HEADS 8
#define HID 8
#define OUT_DIM 40
#define EMAX 1700000
#define NEG_SLOPE 0.2f
#define SCAN_B 1024

// ---------------- scratch ---------------------------------------------------------
__device__ float g_x1[NPAD * 128];    // [xl | xr] combined, stride 128
__device__ float g_out1[NPAD * 64];
__device__ float g_h2[NPAD * 80];     // [hl | hr] combined, stride 80

__device__ int g_cnt[NN];
__device__ int g_incl[NN];
__device__ int g_blksum[128];
__device__ int g_offs[NN + 1];
__device__ int g_cursor[NN];
__device__ int g_csr_src[EMAX];

// ---------------- CSR build -------------------------------------------------------
__global__ void csr_init() {
    int i = blockIdx.x * blockDim.x + threadIdx.x;
    if (i < NN) g_cnt[i] = 1;    // self loop
}

__global__ void csr_hist(const int* __restrict__ ei, int E) {
    int e = blockIdx.x * blockDim.x + threadIdx.x;
    if (e < E) atomicAdd(&g_cnt[ei[E + e]], 1);
}

__global__ void scan1() {
    __shared__ int sm[SCAN_B];
    int i = blockIdx.x * SCAN_B + threadIdx.x;
    int v = (i < NN) ? g_cnt[i] : 0;
    sm[threadIdx.x] = v;
    __syncthreads();
    for (int off = 1; off < SCAN_B; off <<= 1) {
        int t = (threadIdx.x >= off) ? sm[threadIdx.x - off] : 0;
        __syncthreads();
        sm[threadIdx.x] += t;
        __syncthreads();
    }
    if (i < NN) g_incl[i] = sm[threadIdx.x];
    if (threadIdx.x == SCAN_B - 1) g_blksum[blockIdx.x] = sm[threadIdx.x];
}

__global__ void scan3(int nb) {
    __shared__ int bs[128];
    int tid = threadIdx.x;
    if (tid < 128) bs[tid] = (tid < nb) ? g_blksum[tid] : 0;
    __syncthreads();
    for (int off = 1; off < 128; off <<= 1) {
        int t = 0;
        if (tid < 128 && tid >= off) t = bs[tid - off];
        __syncthreads();
        if (tid < 128) bs[tid] += t;
        __syncthreads();
    }
    int i = blockIdx.x * 128 + tid;
    if (tid >= 128 || i >= NN) return;
    int blk = i / SCAN_B;
    int add = (blk > 0) ? bs[blk - 1] : 0;
    int tot = g_incl[i] + add;
    g_offs[i + 1] = tot;
    g_cursor[i] = tot - g_cnt[i];
    if (i == 0) g_offs[0] = 0;
}

__global__ void csr_scatter(const int* __restrict__ ei, int E, int Etot) {
    int e = blockIdx.x * blockDim.x + threadIdx.x;
    if (e >= Etot) return;
    int src, dst;
    if (e < E) { src = ei[e]; dst = ei[E + e]; } else { src = dst = e - E; }
    int pos = atomicAdd(&g_cursor[dst], 1);
    g_csr_src[pos] = src;
}

// ---------------- GEMM1 (tf32 wmma, 64x128 tile, cp.async 2-stage) ---------------
// X[N,256] @ [Wl|Wr] -> g_x1[N,128].  8 warps: 4 row-groups x 2 col-groups,
// warp tile 16x64 (acc = 32 regs) -> 85-reg cap, 3 blocks/SM.
#define ASTRIDE 40
#define BSTRIDE 136
#define A_ST (64 * ASTRIDE)
#define B_ST (32 * BSTRIDE)
#define G1_SMEM ((2 * A_ST + 2 * B_ST) * 4)

__global__ void __launch_bounds__(256, 3)
gemm1_tc(const float* __restrict__ x,
         const float* __restrict__ Wl,
         const float* __restrict__ Wr) {
    extern __shared__ float smem[];
    float* Asm = smem;               // 2 stages of [64][ASTRIDE]
    float* Bsm = smem + 2 * A_ST;    // 2 stages of [32][BSTRIDE]

    const int tid = threadIdx.x;
    const int w = tid >> 5;
    const int warp_m = w & 3;        // rows warp_m*16
    const int warp_n = w >> 2;       // cols warp_n*64
    const int block_row = blockIdx.x * 64;

    // copy slots: A 64x32 (4 threads/row, 8 floats each); B 32x128 (8/row, 16 each)
    const int ar = tid >> 2;
    const int ac = (tid & 3) * 8;
    const int br_ = tid >> 3;
    const int bc = (tid & 7) * 16;

    auto load_stage = [&](int s, int k0) {
        int gr = min(block_row + ar, NN - 1);
        const float* asrc = x + (size_t)gr * IN_DIM + k0 + ac;
        float* adst = Asm + s * A_ST + ar * ASTRIDE + ac;
        __pipeline_memcpy_async(adst,     asrc,     16);
        __pipeline_memcpy_async(adst + 4, asrc + 4, 16);
        const float* bsrc = (bc < 64) ? (Wl + (size_t)(k0 + br_) * 64 + bc)
                                      : (Wr + (size_t)(k0 + br_) * 64 + bc - 64);
        float* bdst = Bsm + s * B_ST + br_ * BSTRIDE + bc;
#pragma unroll
        for (int i = 0; i < 4; i++)
            __pipeline_memcpy_async(bdst + i * 4, bsrc + i * 4, 16);
    };

    wmma::fragment<wmma::accumulator, 16, 16, 8, float> acc[4];
#pragma unroll
    for (int nt = 0; nt < 4; nt++) wmma::fill_fragment(acc[nt], 0.f);

    load_stage(0, 0);
    __pipeline_commit();

    int s = 0;
    for (int k0 = 0; k0 < IN_DIM; k0 += 32) {
        if (k0 + 32 < IN_DIM) load_stage(s ^ 1, k0 + 32);
        __pipeline_commit();
        __pipeline_wait_prior(1);
        __syncthreads();

        const float* Acur = Asm + s * A_ST;
        const float* Bcur = Bsm + s * B_ST;
#pragma unroll
        for (int kk = 0; kk < 32; kk += 8) {
            wmma::fragment<wmma::matrix_a, 16, 16, 8, wmma::precision::tf32, wmma::row_major> af;
            wmma::load_matrix_sync(af, Acur + (warp_m * 16) * ASTRIDE + kk, ASTRIDE);
#pragma unroll
            for (int nt = 0; nt < 4; nt++) {
                wmma::fragment<wmma::matrix_b, 16, 16, 8, wmma::precision::tf32, wmma::row_major> bf;
                wmma::load_matrix_sync(bf, Bcur + kk * BSTRIDE + warp_n * 64 + nt * 16, BSTRIDE);
                wmma::mma_sync(acc[nt], af, bf, acc[nt]);
            }
        }
        __syncthreads();
        s ^= 1;
    }

    int r0 = block_row + warp_m * 16;
#pragma unroll
    for (int nt = 0; nt < 4; nt++) {
        int c0 = warp_n * 64 + nt * 16;
        wmma::store_matrix_sync(g_x1 + (size_t)r0 * 128 + c0, acc[nt],
                                128, wmma::mem_row_major);
    }
}

// ---------------- layer1 fused: warp per dst, depth-3 gather pipeline ------------
__global__ void l1_fused(const float* __restrict__ att,
                         const float* __restrict__ bl, const float* __restrict__ br) {
    int w = (blockIdx.x * blockDim.x + threadIdx.x) >> 5;
    int lane = threadIdx.x & 31;
    if (w >= NN) return;
    const int dst = w;
    const int beg = g_offs[dst], end = g_offs[dst + 1];

    float bl0 = __ldg(bl + lane * 2), bl1 = __ldg(bl + lane * 2 + 1);
    float2 xr = *(const float2*)(g_x1 + (size_t)dst * 128 + 64 + lane * 2);
    xr.x += __ldg(br + lane * 2); xr.y += __ldg(br + lane * 2 + 1);
    float a0 = __ldg(att + lane * 2);
    float a1 = __ldg(att + lane * 2 + 1);

    float acc0 = 0.f, acc1 = 0.f, s = 0.f;

    for (int base = beg; base < end; base += 32) {
        int mysrc = (base + lane < end) ? g_csr_src[base + lane] : 0;
        int cnt = min(32, end - base);

        int s0 = __shfl_sync(0xffffffffu, mysrc, 0);
        float2 q0 = *(const float2*)(g_x1 + (size_t)s0 * 128 + lane * 2);
        float2 q1 = q0;
        if (cnt > 1) {
            int s1 = __shfl_sync(0xffffffffu, mysrc, 1);
            q1 = *(const float2*)(g_x1 + (size_t)s1 * 128 + lane * 2);
        }
        for (int j = 0; j < cnt; j++) {
            float2 xl = q0;
            q0 = q1;
            if (j + 2 < cnt) {
                int sn = __shfl_sync(0xffffffffu, mysrc, j + 2);
                q1 = *(const float2*)(g_x1 + (size_t)sn * 128 + lane * 2);
            }
            xl.x += bl0; xl.y += bl1;
            float m0 = xl.x + xr.x, m1 = xl.y + xr.y;
            float l0 = m0 > 0.f ? m0 : NEG_SLOPE * m0;
            float l1 = m1 > 0.f ? m1 : NEG_SLOPE * m1;
            float p = l0 * a0 + l1 * a1;
            p += __shfl_xor_sync(0xffffffffu, p, 1);
            p += __shfl_xor_sync(0xffffffffu, p, 2);
            float ev = __expf(p);
            acc0 += ev * xl.x; acc1 += ev * xl.y; s += ev;
        }
    }
    float inv = 1.f / s;
    *(float2*)(g_out1 + (size_t)dst * 64 + lane * 2) = make_float2(acc0 * inv, acc1 * inv);
}

// ---------------- GEMM2 (tf32 wmma): elu(out1+bias1)[N,64] @ [Wl2|Wr2] -> g_h2 ---
#define A2STRIDE 68
#define B2STRIDE 88

__global__ void gemm2_tc(const float* __restrict__ bias1,
                         const float* __restrict__ Wl2,
                         const float* __restrict__ Wr2) {
    __shared__ float As[64][A2STRIDE];
    __shared__ float Bs[64][B2STRIDE];
    const int tid = threadIdx.x;   // 128 threads
    const int w = tid >> 5;
    const int node0 = blockIdx.x * 64;

#pragma unroll
    for (int i = 0; i < 8; i++) {
        int f = tid + i * 128;
        int r = f >> 4, c = (f & 15) * 4;
        float4 v = *(const float4*)(g_out1 + (size_t)(node0 + r) * 64 + c);
        float4 b = *(const float4*)(bias1 + c);
        v.x += b.x; v.y += b.y; v.z += b.z; v.w += b.w;
        v.x = v.x > 0.f ? v.x : (__expf(v.x) - 1.f);
        v.y = v.y > 0.f ? v.y : (__expf(v.y) - 1.f);
        v.z = v.z > 0.f ? v.z : (__expf(v.z) - 1.f);
        v.w = v.w > 0.f ? v.w : (__expf(v.w) - 1.f);
        As[r][c + 0] = wmma::__float_to_tf32(v.x);
        As[r][c + 1] = wmma::__float_to_tf32(v.y);
        As[r][c + 2] = wmma::__float_to_tf32(v.z);
        As[r][c + 3] = wmma::__float_to_tf32(v.w);
    }
#pragma unroll
    for (int i = 0; i < 10; i++) {
        int f = tid + i * 128;
        int r = f / 20, c = (f % 20) * 4;
        const float* src = (c < 40) ? (Wl2 + (size_t)r * 40 + c)
                                    : (Wr2 + (size_t)r * 40 + c - 40);
        float4 v = *(const float4*)src;
        Bs[r][c + 0] = wmma::__float_to_tf32(v.x);
        Bs[r][c + 1] = wmma::__float_to_tf32(v.y);
        Bs[r][c + 2] = wmma::__float_to_tf32(v.z);
        Bs[r][c + 3] = wmma::__float_to_tf32(v.w);
    }
    __syncthreads();

    wmma::fragment<wmma::accumulator, 16, 16, 8, float> acc[5];
#pragma unroll
    for (int nt = 0; nt < 5; nt++) wmma::fill_fragment(acc[nt], 0.f);

#pragma unroll
    for (int kk = 0; kk < 64; kk += 8) {
        wmma::fragment<wmma::matrix_a, 16, 16, 8, wmma::precision::tf32, wmma::row_major> af;
        wmma::load_matrix_sync(af, &As[w * 16][kk], A2STRIDE);
#pragma unroll
        for (int nt = 0; nt < 5; nt++) {
            wmma::fragment<wmma::matrix_b, 16, 16, 8, wmma::precision::tf32, wmma::row_major> bf;
            wmma::load_matrix_sync(bf, &Bs[kk][nt * 16], B2STRIDE);
            wmma::mma_sync(acc[nt], af, bf, acc[nt]);
        }
    }

    int r0 = node0 + w * 16;
#pragma unroll
    for (int nt = 0; nt < 5; nt++)
        wmma::store_matrix_sync(g_h2 + (size_t)r0 * 80 + nt * 16, acc[nt],
                                80, wmma::mem_row_major);
}

// ---------------- layer2 fused + final log_softmax: warp per dst ----------------
__global__ void l2_final(const float* __restrict__ att,
                         const float* __restrict__ bl2, const float* __restrict__ br2,
                         const float* __restrict__ bias2, float* __restrict__ out) {
    int w = (blockIdx.x * blockDim.x + threadIdx.x) >> 5;
    int lane = threadIdx.x & 31;
    if (w >= NN) return;
    const int dst = w;
    const int beg = g_offs[dst], end = g_offs[dst + 1];
    const bool act = lane < 20;

    float bl0 = act ? __ldg(bl2 + lane * 2)     : 0.f;
    float bl1 = act ? __ldg(bl2 + lane * 2 + 1) : 0.f;
    float2 hr = act ? *(const float2*)(g_h2 + (size_t)dst * 80 + 40 + lane * 2)
                    : make_float2(0.f, 0.f);
    if (act) { hr.x += __ldg(br2 + lane * 2); hr.y += __ldg(br2 + lane * 2 + 1); }
    float a0 = act ? __ldg(att + lane * 2)     : 0.f;
    float a1 = act ? __ldg(att + lane * 2 + 1) : 0.f;

    float acc0 = 0.f, acc1 = 0.f, s = 0.f;

    for (int base = beg; base < end; base += 32) {
        int mysrc = (base + lane < end) ? g_csr_src[base + lane] : 0;
        int cnt = min(32, end - base);

        int s0 = __shfl_sync(0xffffffffu, mysrc, 0);
        float2 q0 = act ? *(const float2*)(g_h2 + (size_t)s0 * 80 + lane * 2)
                        : make_float2(0.f, 0.f);
        float2 q1 = q0;
        if (cnt > 1) {
            int s1 = __shfl_sync(0xffffffffu, mysrc, 1);
            if (act) q1 = *(const float2*)(g_h2 + (size_t)s1 * 80 + lane * 2);
        }
        for (int j = 0; j < cnt; j++) {
            float2 hl = q0;
            q0 = q1;
            if (j + 2 < cnt) {
                int sn = __shfl_sync(0xffffffffu, mysrc, j + 2);
                if (act) q1 = *(const float2*)(g_h2 + (size_t)sn * 80 + lane * 2);
            }
            hl.x += bl0; hl.y += bl1;
            float m0 = hl.x + hr.x, m1 = hl.y + hr.y;
            float l0 = m0 > 0.f ? m0 : NEG_SLOPE * m0;
            float l1 = m1 > 0.f ? m1 : NEG_SLOPE * m1;
            float p = l0 * a0 + l1 * a1;
#pragma unroll
            for (int off = 16; off > 0; off >>= 1)
                p += __shfl_xor_sync(0xffffffffu, p, off);
            float ev = __expf(p);
            acc0 += ev * hl.x; acc1 += ev * hl.y; s += ev;
        }
    }
    float inv = 1.f / s;
    float v0 = acc0 * inv, v1 = acc1 * inv;
    if (act) {
        v0 += __ldg(bias2 + lane * 2);
        v1 += __ldg(bias2 + lane * 2 + 1);
    }
    float m = act ? fmaxf(v0, v1) : -FLT_MAX;
#pragma unroll
    for (int off = 16; off > 0; off >>= 1)
        m = fmaxf(m, __shfl_xor_sync(0xffffffffu, m, off));
    float se = act ? (__expf(v0 - m) + __expf(v1 - m)) : 0.f;
#pragma unroll
    for (int off = 16; off > 0; off >>= 1)
        se += __shfl_xor_sync(0xffffffffu, se, off);
    float lse = m + logf(se);
    if (act)
        *(float2*)(out + (size_t)dst * 40 + lane * 2) = make_float2(v0 - lse, v1 - lse);
}

// ---------------- launch ----------------------------------------------------------
extern "C" void kernel_launch(void* const* d_in, const int* in_sizes, int n_in,
                              void* d_out, int out_size) {
    const float* x    = (const float*)d_in[0];
    const int*   ei   = (const int*)  d_in[1];
    const float* Wl1  = (const float*)d_in[2];
    const float* bl1  = (const float*)d_in[3];
    const float* Wr1  = (const float*)d_in[4];
    const float* br1  = (const float*)d_in[5];
    const float* att1 = (const float*)d_in[6];
    const float* bias1= (const float*)d_in[7];
    const float* Wl2  = (const float*)d_in[8];
    const float* bl2  = (const float*)d_in[9];
    const float* Wr2  = (const float*)d_in[10];
    const float* br2  = (const float*)d_in[11];
    const float* att2 = (const float*)d_in[12];
    const float* bias2= (const float*)d_in[13];
    float* out = (float*)d_out;

    const int E = in_sizes[1] / 2;
    const int Etot = E + NN;
    const int nb = (NN + SCAN_B - 1) / SCAN_B;

    // lazily-created side stream + fork/join events (host resources only)
    static cudaStream_t s2 = nullptr;
    static cudaEvent_t evA = nullptr, evB = nullptr;
    if (s2 == nullptr) {
        cudaStreamCreateWithFlags(&s2, cudaStreamNonBlocking);
        cudaEventCreateWithFlags(&evA, cudaEventDisableTiming);
        cudaEventCreateWithFlags(&evB, cudaEventDisableTiming);
    }

    cudaFuncSetAttribute(gemm1_tc, cudaFuncAttributeMaxDynamicSharedMemorySize, G1_SMEM);

    // fork: CSR build on s2 runs concurrently with gemm1 on the main stream
    cudaEventRecord(evA, 0);
    cudaStreamWaitEvent(s2, evA, 0);

    gemm1_tc<<<NPAD / 64, 256, G1_SMEM>>>(x, Wl1, Wr1);           // main stream

    csr_init<<<(NN + 255) / 256, 256, 0, s2>>>();
    csr_hist<<<(E + 255) / 256, 256, 0, s2>>>(ei, E);
    scan1<<<nb, SCAN_B, 0, s2>>>();
    scan3<<<(NN + 127) / 128, 128, 0, s2>>>(nb);
    csr_scatter<<<(Etot + 255) / 256, 256, 0, s2>>>(ei, E, Etot);

    cudaEventRecord(evB, s2);
    cudaStreamWaitEvent(0, evB, 0);   // join before the consumers

    l1_fused<<<(NN * 32 + 255) / 256, 256>>>(att1, bl1, br1);
    gemm2_tc<<<NPAD / 64, 128>>>(bias1, Wl2, Wr2);
    l2_final<<<(NN * 32 + 255) / 256, 256>>>(att2, bl2, br2, bias2, out);
}

// round 10
// speedup vs baseline: 3.1354x; 1.0429x over previous
#include <cuda_runtime.h>
#include <cuda_bf16.h>
#include <cuda_pipeline.h>
#include <mma.h>
#include <math.h>
#include <float.h>

using namespace nvcuda;

#define NN 100000
#define NPAD 100096    // multiple of 128 (and 64)
#define IN_DIM 256
#define L1_OUT 64
#define HEADS 8
#define HID 8
#define OUT_DIM 40
#define EMAX 1700000
#define NEG_SLOPE 0.2f
#define SCAN_B 1024

// ---------------- scratch ---------------------------------------------------------
__device__ float g_x1[NPAD * 128];    // [xl | xr] combined, stride 128
__device__ float g_out1[NPAD * 64];
__device__ float g_h2[NPAD * 80];     // [hl | hr] combined, stride 80

__device__ int g_cnt[NN];
__device__ int g_incl[NN];
__device__ int g_blksum[128];
__device__ int g_offs[NN + 1];
__device__ int g_cursor[NN];
__device__ int g_csr_src[EMAX];

// ---------------- CSR build -------------------------------------------------------
__global__ void csr_init() {
    int i = blockIdx.x * blockDim.x + threadIdx.x;
    if (i < NN) g_cnt[i] = 1;    // self loop
}

__global__ void csr_hist(const int* __restrict__ ei, int E) {
    int e = blockIdx.x * blockDim.x + threadIdx.x;
    if (e < E) atomicAdd(&g_cnt[ei[E + e]], 1);
}

__global__ void scan1() {
    __shared__ int sm[SCAN_B];
    int i = blockIdx.x * SCAN_B + threadIdx.x;
    int v = (i < NN) ? g_cnt[i] : 0;
    sm[threadIdx.x] = v;
    __syncthreads();
    for (int off = 1; off < SCAN_B; off <<= 1) {
        int t = (threadIdx.x >= off) ? sm[threadIdx.x - off] : 0;
        __syncthreads();
        sm[threadIdx.x] += t;
        __syncthreads();
    }
    if (i < NN) g_incl[i] = sm[threadIdx.x];
    if (threadIdx.x == SCAN_B - 1) g_blksum[blockIdx.x] = sm[threadIdx.x];
}

__global__ void scan3(int nb) {
    __shared__ int bs[128];
    int tid = threadIdx.x;
    if (tid < 128) bs[tid] = (tid < nb) ? g_blksum[tid] : 0;
    __syncthreads();
    for (int off = 1; off < 128; off <<= 1) {
        int t = 0;
        if (tid < 128 && tid >= off) t = bs[tid - off];
        __syncthreads();
        if (tid < 128) bs[tid] += t;
        __syncthreads();
    }
    int i = blockIdx.x * 128 + tid;
    if (tid >= 128 || i >= NN) return;
    int blk = i / SCAN_B;
    int add = (blk > 0) ? bs[blk - 1] : 0;
    int tot = g_incl[i] + add;
    g_offs[i + 1] = tot;
    g_cursor[i] = tot - g_cnt[i];
    if (i == 0) g_offs[0] = 0;
}

__global__ void csr_scatter(const int* __restrict__ ei, int E, int Etot) {
    int e = blockIdx.x * blockDim.x + threadIdx.x;
    if (e >= Etot) return;
    int src, dst;
    if (e < E) { src = ei[e]; dst = ei[E + e]; } else { src = dst = e - E; }
    int pos = atomicAdd(&g_cursor[dst], 1);
    g_csr_src[pos] = src;
}

// ---------------- GEMM1 (tf32 wmma, 64x128 tile, cp.async 2-stage) ---------------
#define ASTRIDE 40
#define BSTRIDE 136
#define A_ST (64 * ASTRIDE)
#define B_ST (32 * BSTRIDE)
#define G1_SMEM ((2 * A_ST + 2 * B_ST) * 4)

__global__ void __launch_bounds__(256, 3)
gemm1_tc(const float* __restrict__ x,
         const float* __restrict__ Wl,
         const float* __restrict__ Wr) {
    extern __shared__ float smem[];
    float* Asm = smem;
    float* Bsm = smem + 2 * A_ST;

    const int tid = threadIdx.x;
    const int w = tid >> 5;
    const int warp_m = w & 3;
    const int warp_n = w >> 2;
    const int block_row = blockIdx.x * 64;

    const int ar = tid >> 2;
    const int ac = (tid & 3) * 8;
    const int br_ = tid >> 3;
    const int bc = (tid & 7) * 16;

    auto load_stage = [&](int s, int k0) {
        int gr = min(block_row + ar, NN - 1);
        const float* asrc = x + (size_t)gr * IN_DIM + k0 + ac;
        float* adst = Asm + s * A_ST + ar * ASTRIDE + ac;
        __pipeline_memcpy_async(adst,     asrc,     16);
        __pipeline_memcpy_async(adst + 4, asrc + 4, 16);
        const float* bsrc = (bc < 64) ? (Wl + (size_t)(k0 + br_) * 64 + bc)
                                      : (Wr + (size_t)(k0 + br_) * 64 + bc - 64);
        float* bdst = Bsm + s * B_ST + br_ * BSTRIDE + bc;
#pragma unroll
        for (int i = 0; i < 4; i++)
            __pipeline_memcpy_async(bdst + i * 4, bsrc + i * 4, 16);
    };

    wmma::fragment<wmma::accumulator, 16, 16, 8, float> acc[4];
#pragma unroll
    for (int nt = 0; nt < 4; nt++) wmma::fill_fragment(acc[nt], 0.f);

    load_stage(0, 0);
    __pipeline_commit();

    int s = 0;
    for (int k0 = 0; k0 < IN_DIM; k0 += 32) {
        if (k0 + 32 < IN_DIM) load_stage(s ^ 1, k0 + 32);
        __pipeline_commit();
        __pipeline_wait_prior(1);
        __syncthreads();

        const float* Acur = Asm + s * A_ST;
        const float* Bcur = Bsm + s * B_ST;
#pragma unroll
        for (int kk = 0; kk < 32; kk += 8) {
            wmma::fragment<wmma::matrix_a, 16, 16, 8, wmma::precision::tf32, wmma::row_major> af;
            wmma::load_matrix_sync(af, Acur + (warp_m * 16) * ASTRIDE + kk, ASTRIDE);
#pragma unroll
            for (int nt = 0; nt < 4; nt++) {
                wmma::fragment<wmma::matrix_b, 16, 16, 8, wmma::precision::tf32, wmma::row_major> bf;
                wmma::load_matrix_sync(bf, Bcur + kk * BSTRIDE + warp_n * 64 + nt * 16, BSTRIDE);
                wmma::mma_sync(acc[nt], af, bf, acc[nt]);
            }
        }
        __syncthreads();
        s ^= 1;
    }

    int r0 = block_row + warp_m * 16;
#pragma unroll
    for (int nt = 0; nt < 4; nt++) {
        int c0 = warp_n * 64 + nt * 16;
        wmma::store_matrix_sync(g_x1 + (size_t)r0 * 128 + c0, acc[nt],
                                128, wmma::mem_row_major);
    }
}

// ---------------- layer1 fused: warp per dst, 4 edge-groups x 8 lanes ------------
// Lane (g,i): edge-group g handles edges j*4..; lane owns head i (dims 8i..8i+7).
// Per-head logit is LOCAL (no shuffles in the inner loop).
__global__ void l1_fused(const float* __restrict__ att,
                         const float* __restrict__ bl, const float* __restrict__ br) {
    int w = (blockIdx.x * blockDim.x + threadIdx.x) >> 5;
    int lane = threadIdx.x & 31;
    if (w >= NN) return;
    const int dst = w;
    const int g = lane >> 3;
    const int i = lane & 7;
    const int beg = g_offs[dst], end = g_offs[dst + 1];

    float4 bl0 = *(const float4*)(bl + i * 8);
    float4 bl1 = *(const float4*)(bl + i * 8 + 4);
    float4 a0  = *(const float4*)(att + i * 8);
    float4 a1  = *(const float4*)(att + i * 8 + 4);
    float4 xr0 = *(const float4*)(g_x1 + (size_t)dst * 128 + 64 + i * 8);
    float4 xr1 = *(const float4*)(g_x1 + (size_t)dst * 128 + 64 + i * 8 + 4);
    {   // xr += br
        float4 r0 = *(const float4*)(br + i * 8);
        float4 r1 = *(const float4*)(br + i * 8 + 4);
        xr0.x += r0.x; xr0.y += r0.y; xr0.z += r0.z; xr0.w += r0.w;
        xr1.x += r1.x; xr1.y += r1.y; xr1.z += r1.z; xr1.w += r1.w;
    }

    float4 A0 = {0,0,0,0}, A1 = {0,0,0,0};
    float s = 0.f;

    for (int base = beg; base < end; base += 32) {
        int mysrc = (base + lane < end) ? g_csr_src[base + lane] : 0;
        int cnt = min(32, end - base);
        int nj = (cnt + 3) >> 2;

        // depth-2 pipeline per group: prefetch edge j=0
        int e0 = g;
        int sp = __shfl_sync(0xffffffffu, mysrc, e0);
        bool actp = e0 < cnt;
        float4 p0 = {0,0,0,0}, p1 = {0,0,0,0};
        if (actp) {
            p0 = *(const float4*)(g_x1 + (size_t)sp * 128 + i * 8);
            p1 = *(const float4*)(g_x1 + (size_t)sp * 128 + i * 8 + 4);
        }
        for (int j = 0; j < nj; j++) {
            float4 q0 = p0, q1 = p1;
            bool act = actp;
            int e1 = (j + 1) * 4 + g;
            int sn = __shfl_sync(0xffffffffu, mysrc, e1 & 31);   // convergent
            actp = e1 < cnt;
            p0 = make_float4(0,0,0,0); p1 = make_float4(0,0,0,0);
            if (actp) {
                p0 = *(const float4*)(g_x1 + (size_t)sn * 128 + i * 8);
                p1 = *(const float4*)(g_x1 + (size_t)sn * 128 + i * 8 + 4);
            }
            // xl + bias
            q0.x += bl0.x; q0.y += bl0.y; q0.z += bl0.z; q0.w += bl0.w;
            q1.x += bl1.x; q1.y += bl1.y; q1.z += bl1.z; q1.w += bl1.w;
            // m = xl + xr; leaky; local 8-dim dot with att
            float p = 0.f;
            {
                float m;
                m = q0.x + xr0.x; p += (m > 0.f ? m : NEG_SLOPE * m) * a0.x;
                m = q0.y + xr0.y; p += (m > 0.f ? m : NEG_SLOPE * m) * a0.y;
                m = q0.z + xr0.z; p += (m > 0.f ? m : NEG_SLOPE * m) * a0.z;
                m = q0.w + xr0.w; p += (m > 0.f ? m : NEG_SLOPE * m) * a0.w;
                m = q1.x + xr1.x; p += (m > 0.f ? m : NEG_SLOPE * m) * a1.x;
                m = q1.y + xr1.y; p += (m > 0.f ? m : NEG_SLOPE * m) * a1.y;
                m = q1.z + xr1.z; p += (m > 0.f ? m : NEG_SLOPE * m) * a1.z;
                m = q1.w + xr1.w; p += (m > 0.f ? m : NEG_SLOPE * m) * a1.w;
            }
            float ev = act ? __expf(p) : 0.f;
            A0.x += ev * q0.x; A0.y += ev * q0.y; A0.z += ev * q0.z; A0.w += ev * q0.w;
            A1.x += ev * q1.x; A1.y += ev * q1.y; A1.z += ev * q1.z; A1.w += ev * q1.w;
            s += ev;
        }
    }

    // cross-group reduce (groups differ in lane bits 3-4)
#pragma unroll
    for (int mk = 8; mk <= 16; mk <<= 1) {
        A0.x += __shfl_xor_sync(0xffffffffu, A0.x, mk);
        A0.y += __shfl_xor_sync(0xffffffffu, A0.y, mk);
        A0.z += __shfl_xor_sync(0xffffffffu, A0.z, mk);
        A0.w += __shfl_xor_sync(0xffffffffu, A0.w, mk);
        A1.x += __shfl_xor_sync(0xffffffffu, A1.x, mk);
        A1.y += __shfl_xor_sync(0xffffffffu, A1.y, mk);
        A1.z += __shfl_xor_sync(0xffffffffu, A1.z, mk);
        A1.w += __shfl_xor_sync(0xffffffffu, A1.w, mk);
        s    += __shfl_xor_sync(0xffffffffu, s,    mk);
    }
    if (g == 0) {
        float inv = 1.f / s;
        float4 o0 = make_float4(A0.x * inv, A0.y * inv, A0.z * inv, A0.w * inv);
        float4 o1 = make_float4(A1.x * inv, A1.y * inv, A1.z * inv, A1.w * inv);
        *(float4*)(g_out1 + (size_t)dst * 64 + i * 8)     = o0;
        *(float4*)(g_out1 + (size_t)dst * 64 + i * 8 + 4) = o1;
    }
}

// ---------------- GEMM2 (tf32 wmma): elu(out1+bias1)[N,64] @ [Wl2|Wr2] -> g_h2 ---
#define A2STRIDE 68
#define B2STRIDE 88

__global__ void gemm2_tc(const float* __restrict__ bias1,
                         const float* __restrict__ Wl2,
                         const float* __restrict__ Wr2) {
    __shared__ float As[64][A2STRIDE];
    __shared__ float Bs[64][B2STRIDE];
    const int tid = threadIdx.x;   // 128 threads
    const int w = tid >> 5;
    const int node0 = blockIdx.x * 64;

#pragma unroll
    for (int i = 0; i < 8; i++) {
        int f = tid + i * 128;
        int r = f >> 4, c = (f & 15) * 4;
        float4 v = *(const float4*)(g_out1 + (size_t)(node0 + r) * 64 + c);
        float4 b = *(const float4*)(bias1 + c);
        v.x += b.x; v.y += b.y; v.z += b.z; v.w += b.w;
        v.x = v.x > 0.f ? v.x : (__expf(v.x) - 1.f);
        v.y = v.y > 0.f ? v.y : (__expf(v.y) - 1.f);
        v.z = v.z > 0.f ? v.z : (__expf(v.z) - 1.f);
        v.w = v.w > 0.f ? v.w : (__expf(v.w) - 1.f);
        As[r][c + 0] = wmma::__float_to_tf32(v.x);
        As[r][c + 1] = wmma::__float_to_tf32(v.y);
        As[r][c + 2] = wmma::__float_to_tf32(v.z);
        As[r][c + 3] = wmma::__float_to_tf32(v.w);
    }
#pragma unroll
    for (int i = 0; i < 10; i++) {
        int f = tid + i * 128;
        int r = f / 20, c = (f % 20) * 4;
        const float* src = (c < 40) ? (Wl2 + (size_t)r * 40 + c)
                                    : (Wr2 + (size_t)r * 40 + c - 40);
        float4 v = *(const float4*)src;
        Bs[r][c + 0] = wmma::__float_to_tf32(v.x);
        Bs[r][c + 1] = wmma::__float_to_tf32(v.y);
        Bs[r][c + 2] = wmma::__float_to_tf32(v.z);
        Bs[r][c + 3] = wmma::__float_to_tf32(v.w);
    }
    __syncthreads();

    wmma::fragment<wmma::accumulator, 16, 16, 8, float> acc[5];
#pragma unroll
    for (int nt = 0; nt < 5; nt++) wmma::fill_fragment(acc[nt], 0.f);

#pragma unroll
    for (int kk = 0; kk < 64; kk += 8) {
        wmma::fragment<wmma::matrix_a, 16, 16, 8, wmma::precision::tf32, wmma::row_major> af;
        wmma::load_matrix_sync(af, &As[w * 16][kk], A2STRIDE);
#pragma unroll
        for (int nt = 0; nt < 5; nt++) {
            wmma::fragment<wmma::matrix_b, 16, 16, 8, wmma::precision::tf32, wmma::row_major> bf;
            wmma::load_matrix_sync(bf, &Bs[kk][nt * 16], B2STRIDE);
            wmma::mma_sync(acc[nt], af, bf, acc[nt]);
        }
    }

    int r0 = node0 + w * 16;
#pragma unroll
    for (int nt = 0; nt < 5; nt++)
        wmma::store_matrix_sync(g_h2 + (size_t)r0 * 80 + nt * 16, acc[nt],
                                80, wmma::mem_row_major);
}

// ---------------- layer2 fused + log_softmax: 4 edge-groups x 8 lanes x 5 dims ---
__global__ void l2_final(const float* __restrict__ att,
                         const float* __restrict__ bl2, const float* __restrict__ br2,
                         const float* __restrict__ bias2, float* __restrict__ out) {
    int w = (blockIdx.x * blockDim.x + threadIdx.x) >> 5;
    int lane = threadIdx.x & 31;
    if (w >= NN) return;
    const int dst = w;
    const int g = lane >> 3;
    const int i = lane & 7;      // dims 5i..5i+4
    const int beg = g_offs[dst], end = g_offs[dst + 1];

    float a[5], blv[5], hr[5];
#pragma unroll
    for (int k = 0; k < 5; k++) {
        a[k]   = __ldg(att + i * 5 + k);
        blv[k] = __ldg(bl2 + i * 5 + k);
        hr[k]  = g_h2[(size_t)dst * 80 + 40 + i * 5 + k] + __ldg(br2 + i * 5 + k);
    }

    float A[5] = {0,0,0,0,0};
    float s = 0.f;

    for (int base = beg; base < end; base += 32) {
        int mysrc = (base + lane < end) ? g_csr_src[base + lane] : 0;
        int cnt = min(32, end - base);
        int nj = (cnt + 3) >> 2;

        int e0 = g;
        int sp = __shfl_sync(0xffffffffu, mysrc, e0);
        bool actp = e0 < cnt;
        float p0[5] = {0,0,0,0,0};
        if (actp) {
#pragma unroll
            for (int k = 0; k < 5; k++)
                p0[k] = g_h2[(size_t)sp * 80 + i * 5 + k];
        }
        for (int j = 0; j < nj; j++) {
            float hl[5];
            bool act = actp;
#pragma unroll
            for (int k = 0; k < 5; k++) hl[k] = p0[k];

            int e1 = (j + 1) * 4 + g;
            int sn = __shfl_sync(0xffffffffu, mysrc, e1 & 31);
            actp = e1 < cnt;
#pragma unroll
            for (int k = 0; k < 5; k++) p0[k] = 0.f;
            if (actp) {
#pragma unroll
                for (int k = 0; k < 5; k++)
                    p0[k] = g_h2[(size_t)sn * 80 + i * 5 + k];
            }

            float p = 0.f;
#pragma unroll
            for (int k = 0; k < 5; k++) {
                hl[k] += blv[k];
                float m = hl[k] + hr[k];
                p += (m > 0.f ? m : NEG_SLOPE * m) * a[k];
            }
            // intra-group logit reduce (convergent: all 32 lanes participate)
            p += __shfl_xor_sync(0xffffffffu, p, 1);
            p += __shfl_xor_sync(0xffffffffu, p, 2);
            p += __shfl_xor_sync(0xffffffffu, p, 4);
            float ev = act ? __expf(p) : 0.f;
#pragma unroll
            for (int k = 0; k < 5; k++) A[k] += ev * hl[k];
            s += ev;
        }
    }

    // cross-group reduce
#pragma unroll
    for (int mk = 8; mk <= 16; mk <<= 1) {
#pragma unroll
        for (int k = 0; k < 5; k++)
            A[k] += __shfl_xor_sync(0xffffffffu, A[k], mk);
        s += __shfl_xor_sync(0xffffffffu, s, mk);
    }
    float inv = 1.f / s;
    float v[5];
    float mx = -FLT_MAX;
#pragma unroll
    for (int k = 0; k < 5; k++) {
        v[k] = A[k] * inv + __ldg(bias2 + i * 5 + k);
        mx = fmaxf(mx, v[k]);
    }
    mx = fmaxf(mx, __shfl_xor_sync(0xffffffffu, mx, 1));
    mx = fmaxf(mx, __shfl_xor_sync(0xffffffffu, mx, 2));
    mx = fmaxf(mx, __shfl_xor_sync(0xffffffffu, mx, 4));
    float se = 0.f;
#pragma unroll
    for (int k = 0; k < 5; k++) se += __expf(v[k] - mx);
    se += __shfl_xor_sync(0xffffffffu, se, 1);
    se += __shfl_xor_sync(0xffffffffu, se, 2);
    se += __shfl_xor_sync(0xffffffffu, se, 4);
    float lse = mx + logf(se);
    if (g == 0) {
#pragma unroll
        for (int k = 0; k < 5; k++)
            out[(size_t)dst * 40 + i * 5 + k] = v[k] - lse;
    }
}

// ---------------- launch ----------------------------------------------------------
extern "C" void kernel_launch(void* const* d_in, const int* in_sizes, int n_in,
                              void* d_out, int out_size) {
    const float* x    = (const float*)d_in[0];
    const int*   ei   = (const int*)  d_in[1];
    const float* Wl1  = (const float*)d_in[2];
    const float* bl1  = (const float*)d_in[3];
    const float* Wr1  = (const float*)d_in[4];
    const float* br1  = (const float*)d_in[5];
    const float* att1 = (const float*)d_in[6];
    const float* bias1= (const float*)d_in[7];
    const float* Wl2  = (const float*)d_in[8];
    const float* bl2  = (const float*)d_in[9];
    const float* Wr2  = (const float*)d_in[10];
    const float* br2  = (const float*)d_in[11];
    const float* att2 = (const float*)d_in[12];
    const float* bias2= (const float*)d_in[13];
    float* out = (float*)d_out;

    const int E = in_sizes[1] / 2;
    const int Etot = E + NN;
    const int nb = (NN + SCAN_B - 1) / SCAN_B;

    static cudaStream_t s2 = nullptr;
    static cudaEvent_t evA = nullptr, evB = nullptr;
    if (s2 == nullptr) {
        cudaStreamCreateWithFlags(&s2, cudaStreamNonBlocking);
        cudaEventCreateWithFlags(&evA, cudaEventDisableTiming);
        cudaEventCreateWithFlags(&evB, cudaEventDisableTiming);
    }

    cudaFuncSetAttribute(gemm1_tc, cudaFuncAttributeMaxDynamicSharedMemorySize, G1_SMEM);

    cudaEventRecord(evA, 0);
    cudaStreamWaitEvent(s2, evA, 0);

    gemm1_tc<<<NPAD / 64, 256, G1_SMEM>>>(x, Wl1, Wr1);           // main stream

    csr_init<<<(NN + 255) / 256, 256, 0, s2>>>();
    csr_hist<<<(E + 255) / 256, 256, 0, s2>>>(ei, E);
    scan1<<<nb, SCAN_B, 0, s2>>>();
    scan3<<<(NN + 127) / 128, 128, 0, s2>>>(nb);
    csr_scatter<<<(Etot + 255) / 256, 256, 0, s2>>>(ei, E, Etot);

    cudaEventRecord(evB, s2);
    cudaStreamWaitEvent(0, evB, 0);

    l1_fused<<<(NN * 32 + 255) / 256, 256>>>(att1, bl1, br1);
    gemm2_tc<<<NPAD / 64, 128>>>(bias1, Wl2, Wr2);
    l2_final<<<(NN * 32 + 255) / 256, 256>>>(att2, bl2, br2, bias2, out);
}